// round 2
// baseline (speedup 1.0000x reference)
#include <cuda_runtime.h>
#include <math.h>

// Problem constants
#define B_  2
#define S_  2048
#define D_  1024
#define H_  16
#define DH_ 64
#define M_  (B_*S_)          // 4096 rows for projection GEMMs
#define SCALE_ 0.125f        // 64^-0.5

// Scratch buffers (allocation-free rule: __device__ globals)
static __device__ float g_Q[B_*H_*S_*DH_];   // [b][h][s][dh]
static __device__ float g_K[B_*H_*S_*DH_];
static __device__ float g_V[B_*H_*S_*DH_];
static __device__ float g_A[B_*S_*D_];       // attention out, [b][s][h*dh]

// ---------------------------------------------------------------------------
// GEMM: out[m][n] = sum_k X[m][k] * W[n][k]   (X:[4096,1024], W:[1024,1024])
// MODE 0: write to [b][h][s][dh] layout (QKV projections)
// MODE 1: write row-major [m][n] + bias (output projection)
// 64x64 tile, 256 threads, 4x4 micro-tile, BK=16, k-major smem tiles.
// ---------------------------------------------------------------------------
template<int MODE>
__global__ __launch_bounds__(256)
void gemm64(const float* __restrict__ X, const float* __restrict__ W,
            const float* __restrict__ bias, float* __restrict__ out)
{
    __shared__ float Xs[16][64];   // [k][m]
    __shared__ float Ws[16][64];   // [k][n]

    const int m0 = blockIdx.y * 64;
    const int n0 = blockIdx.x * 64;
    const int tid = threadIdx.x;
    const int tx = tid & 15;       // n direction
    const int ty = tid >> 4;       // m direction
    const int lr = tid >> 2;       // 0..63 tile row for loading
    const int lk = (tid & 3) * 4;  // k offset 0,4,8,12

    float acc[4][4];
#pragma unroll
    for (int i = 0; i < 4; i++)
#pragma unroll
        for (int j = 0; j < 4; j++) acc[i][j] = 0.f;

    for (int kt = 0; kt < D_; kt += 16) {
        float4 xv = *(const float4*)(X + (m0 + lr) * D_ + kt + lk);
        float4 wv = *(const float4*)(W + (n0 + lr) * D_ + kt + lk);
        __syncthreads();
        Xs[lk + 0][lr] = xv.x; Xs[lk + 1][lr] = xv.y;
        Xs[lk + 2][lr] = xv.z; Xs[lk + 3][lr] = xv.w;
        Ws[lk + 0][lr] = wv.x; Ws[lk + 1][lr] = wv.y;
        Ws[lk + 2][lr] = wv.z; Ws[lk + 3][lr] = wv.w;
        __syncthreads();
#pragma unroll
        for (int kk = 0; kk < 16; kk++) {
            float4 a = *(const float4*)&Xs[kk][ty * 4];
            float4 b = *(const float4*)&Ws[kk][tx * 4];
            acc[0][0] += a.x * b.x; acc[0][1] += a.x * b.y;
            acc[0][2] += a.x * b.z; acc[0][3] += a.x * b.w;
            acc[1][0] += a.y * b.x; acc[1][1] += a.y * b.y;
            acc[1][2] += a.y * b.z; acc[1][3] += a.y * b.w;
            acc[2][0] += a.z * b.x; acc[2][1] += a.z * b.y;
            acc[2][2] += a.z * b.z; acc[2][3] += a.z * b.w;
            acc[3][0] += a.w * b.x; acc[3][1] += a.w * b.y;
            acc[3][2] += a.w * b.z; acc[3][3] += a.w * b.w;
        }
    }

    if (MODE == 0) {
        // n0 is a multiple of 64 => all 4 cols of a thread are in one head
        const int h = n0 >> 6;             // head index
        const int d = tx * 4;              // dh offset (aligned for float4)
#pragma unroll
        for (int i = 0; i < 4; i++) {
            int m = m0 + ty * 4 + i;
            int b = m / S_;
            int s = m - b * S_;
            float4 v = make_float4(acc[i][0], acc[i][1], acc[i][2], acc[i][3]);
            *(float4*)(out + (((b * H_ + h) * S_ + s) * DH_ + d)) = v;
        }
    } else {
        const int col = n0 + tx * 4;
        float4 bv = *(const float4*)(bias + col);
#pragma unroll
        for (int i = 0; i < 4; i++) {
            int row = m0 + ty * 4 + i;
            float4 v = make_float4(acc[i][0] + bv.x, acc[i][1] + bv.y,
                                   acc[i][2] + bv.z, acc[i][3] + bv.w);
            *(float4*)(out + row * D_ + col) = v;
        }
    }
}

// ---------------------------------------------------------------------------
// Flash-style attention, fp32. One block = 64 query rows of one (b,h).
// Q pre-scaled by SCALE_. Online softmax with 16-lane shfl reductions.
// Smem: Qs[d][q] (16KB) + KPs (K as [d][k], later reused as P [k][q]) (16KB)
//       + Vs[k][d] (16KB) = 48KB static.
// ---------------------------------------------------------------------------
__global__ __launch_bounds__(256)
void attn_kernel(const float* __restrict__ Q, const float* __restrict__ K,
                 const float* __restrict__ V, float* __restrict__ A)
{
    __shared__ float Qs[64 * 64];   // [d][q]
    __shared__ float KPs[64 * 64];  // phase 1: [d][k]; phase 2: P [k][q] (xor-swizzled)
    __shared__ float Vs[64 * 64];   // [k][d]

    const int bh = blockIdx.y;            // 0..31 (b*H + h)
    const int q0 = blockIdx.x * 64;
    const float* Qp = Q + (size_t)bh * S_ * DH_;
    const float* Kp = K + (size_t)bh * S_ * DH_;
    const float* Vp = V + (size_t)bh * S_ * DH_;

    const int tid = threadIdx.x;
    const int tx = tid & 15;   // key/outdim direction
    const int ty = tid >> 4;   // query direction
    const int lr = tid >> 2;       // tile row for loads (0..63)
    const int lc = (tid & 3) * 16; // 16-float chunk base

    // Load Q tile transposed, pre-scaled: Qs[d][q]
#pragma unroll
    for (int u = 0; u < 4; u++) {
        float4 v = *(const float4*)(Qp + (q0 + lr) * DH_ + lc + u * 4);
        Qs[(lc + u * 4 + 0) * 64 + lr] = v.x * SCALE_;
        Qs[(lc + u * 4 + 1) * 64 + lr] = v.y * SCALE_;
        Qs[(lc + u * 4 + 2) * 64 + lr] = v.z * SCALE_;
        Qs[(lc + u * 4 + 3) * 64 + lr] = v.w * SCALE_;
    }

    float m_old[4], l[4], o[4][4];
#pragma unroll
    for (int i = 0; i < 4; i++) {
        m_old[i] = -3.0e38f;
        l[i] = 0.f;
#pragma unroll
        for (int j = 0; j < 4; j++) o[i][j] = 0.f;
    }

    for (int kt = 0; kt < S_; kt += 64) {
        __syncthreads();  // previous iteration done with KPs/Vs (and Q load visible)
        // Load K tile transposed: KPs[d][k]; V tile natural: Vs[k][d]
#pragma unroll
        for (int u = 0; u < 4; u++) {
            float4 kv = *(const float4*)(Kp + (kt + lr) * DH_ + lc + u * 4);
            KPs[(lc + u * 4 + 0) * 64 + lr] = kv.x;
            KPs[(lc + u * 4 + 1) * 64 + lr] = kv.y;
            KPs[(lc + u * 4 + 2) * 64 + lr] = kv.z;
            KPs[(lc + u * 4 + 3) * 64 + lr] = kv.w;
            float4 vv = *(const float4*)(Vp + (kt + lr) * DH_ + lc + u * 4);
            *(float4*)&Vs[lr * 64 + lc + u * 4] = vv;
        }
        __syncthreads();

        // Scores: s[i][j] = sum_d Qs[d][q] * K[d][k]
        float s[4][4];
#pragma unroll
        for (int i = 0; i < 4; i++)
#pragma unroll
            for (int j = 0; j < 4; j++) s[i][j] = 0.f;
#pragma unroll 16
        for (int d = 0; d < 64; d++) {
            float4 a = *(const float4*)&Qs[d * 64 + ty * 4];
            float4 b = *(const float4*)&KPs[d * 64 + tx * 4];
            s[0][0] += a.x * b.x; s[0][1] += a.x * b.y; s[0][2] += a.x * b.z; s[0][3] += a.x * b.w;
            s[1][0] += a.y * b.x; s[1][1] += a.y * b.y; s[1][2] += a.y * b.z; s[1][3] += a.y * b.w;
            s[2][0] += a.z * b.x; s[2][1] += a.z * b.y; s[2][2] += a.z * b.z; s[2][3] += a.z * b.w;
            s[3][0] += a.w * b.x; s[3][1] += a.w * b.y; s[3][2] += a.w * b.z; s[3][3] += a.w * b.w;
        }

        // Online softmax update (reduce over the 16 tx lanes; xor<16 stays in group)
#pragma unroll
        for (int i = 0; i < 4; i++) {
            float mt = fmaxf(fmaxf(s[i][0], s[i][1]), fmaxf(s[i][2], s[i][3]));
            mt = fmaxf(mt, __shfl_xor_sync(0xffffffffu, mt, 1));
            mt = fmaxf(mt, __shfl_xor_sync(0xffffffffu, mt, 2));
            mt = fmaxf(mt, __shfl_xor_sync(0xffffffffu, mt, 4));
            mt = fmaxf(mt, __shfl_xor_sync(0xffffffffu, mt, 8));
            float mn = fmaxf(m_old[i], mt);
            float corr = __expf(m_old[i] - mn);
            float p0 = __expf(s[i][0] - mn);
            float p1 = __expf(s[i][1] - mn);
            float p2 = __expf(s[i][2] - mn);
            float p3 = __expf(s[i][3] - mn);
            float ls = (p0 + p1) + (p2 + p3);
            ls += __shfl_xor_sync(0xffffffffu, ls, 1);
            ls += __shfl_xor_sync(0xffffffffu, ls, 2);
            ls += __shfl_xor_sync(0xffffffffu, ls, 4);
            ls += __shfl_xor_sync(0xffffffffu, ls, 8);
            l[i] = l[i] * corr + ls;
            o[i][0] *= corr; o[i][1] *= corr; o[i][2] *= corr; o[i][3] *= corr;
            m_old[i] = mn;
            s[i][0] = p0; s[i][1] = p1; s[i][2] = p2; s[i][3] = p3;
        }

        __syncthreads();  // everyone done reading KPs as K
        // Write P into KPs as [k][q] with xor swizzle (kills 16-way STS conflict)
#pragma unroll
        for (int j = 0; j < 4; j++) {
            int kcol = tx * 4 + j;
            int base = kcol * 64 + ((ty * 4) ^ ((kcol & 15) << 2));
#pragma unroll
            for (int i = 0; i < 4; i++)
                KPs[base + i] = s[i][j];
        }
        __syncthreads();

        // O += P @ V
#pragma unroll 16
        for (int k = 0; k < 64; k++) {
            float4 p = *(const float4*)&KPs[k * 64 + ((ty * 4) ^ ((k & 15) << 2))];
            float4 v = *(const float4*)&Vs[k * 64 + tx * 4];
            o[0][0] += p.x * v.x; o[0][1] += p.x * v.y; o[0][2] += p.x * v.z; o[0][3] += p.x * v.w;
            o[1][0] += p.y * v.x; o[1][1] += p.y * v.y; o[1][2] += p.y * v.z; o[1][3] += p.y * v.w;
            o[2][0] += p.z * v.x; o[2][1] += p.z * v.y; o[2][2] += p.z * v.z; o[2][3] += p.z * v.w;
            o[3][0] += p.w * v.x; o[3][1] += p.w * v.y; o[3][2] += p.w * v.z; o[3][3] += p.w * v.w;
        }
    }

    // Write out: A[b][s][h*64 + d]
    const int b = bh >> 4;
    const int h = bh & 15;
#pragma unroll
    for (int i = 0; i < 4; i++) {
        float inv = 1.f / l[i];
        int s_idx = q0 + ty * 4 + i;
        float4 v = make_float4(o[i][0] * inv, o[i][1] * inv,
                               o[i][2] * inv, o[i][3] * inv);
        *(float4*)(A + ((size_t)(b * S_ + s_idx) * D_ + h * DH_ + tx * 4)) = v;
    }
}

// ---------------------------------------------------------------------------
extern "C" void kernel_launch(void* const* d_in, const int* in_sizes, int n_in,
                              void* d_out, int out_size)
{
    const float* x  = (const float*)d_in[0];
    const float* Wq = (const float*)d_in[1];
    const float* Wk = (const float*)d_in[2];
    const float* Wv = (const float*)d_in[3];
    const float* Wo = (const float*)d_in[4];
    const float* bo = (const float*)d_in[5];
    float* out = (float*)d_out;

    float *Qb, *Kb, *Vb, *Ab;
    cudaGetSymbolAddress((void**)&Qb, g_Q);
    cudaGetSymbolAddress((void**)&Kb, g_K);
    cudaGetSymbolAddress((void**)&Vb, g_V);
    cudaGetSymbolAddress((void**)&Ab, g_A);

    dim3 gg(D_ / 64, M_ / 64);   // (16, 64)
    gemm64<0><<<gg, 256>>>(x, Wq, nullptr, Qb);
    gemm64<0><<<gg, 256>>>(x, Wk, nullptr, Kb);
    gemm64<0><<<gg, 256>>>(x, Wv, nullptr, Vb);

    attn_kernel<<<dim3(S_ / 64, B_ * H_), 256>>>(Qb, Kb, Vb, Ab);

    gemm64<1><<<gg, 256>>>(Ab, Wo, bo, out);
}

// round 4
// speedup vs baseline: 1.5069x; 1.5069x over previous
#include <cuda_runtime.h>
#include <cuda_bf16.h>
#include <stdint.h>
#include <math.h>

// Problem constants
#define B_  2
#define S_  2048
#define D_  1024
#define H_  16
#define DH_ 64
#define M_  (B_*S_)          // 4096
#define SCALE_ 0.125f

// ---------------------------------------------------------------------------
// Scratch (__device__ globals; allocation-free rule)
// ---------------------------------------------------------------------------
static __device__ float g_Q[B_*H_*S_*DH_];
static __device__ float g_K[B_*H_*S_*DH_];
static __device__ float g_V[B_*H_*S_*DH_];
static __device__ float g_A[B_*S_*D_];
static __device__ __nv_bfloat16 g_Xh[M_*D_], g_Xl[M_*D_];
static __device__ __nv_bfloat16 g_Wh[4*D_*D_], g_Wl[4*D_*D_];
static __device__ __nv_bfloat16 g_Ah[M_*D_], g_Al[M_*D_];

// ---------------------------------------------------------------------------
// Base-ISA tensor-core helpers (mma.sync / ldmatrix / cp.async — no 'a' features)
// ---------------------------------------------------------------------------
__device__ __forceinline__ uint32_t smem_u32(const void* p) {
    uint32_t a;
    asm("{ .reg .u64 t; cvta.to.shared.u64 t, %1; cvt.u32.u64 %0, t; }" : "=r"(a) : "l"(p));
    return a;
}
__device__ __forceinline__ void ldsm4(uint32_t addr, uint32_t* r) {
    asm volatile("ldmatrix.sync.aligned.m8n8.x4.shared.b16 {%0,%1,%2,%3}, [%4];"
                 : "=r"(r[0]), "=r"(r[1]), "=r"(r[2]), "=r"(r[3]) : "r"(addr));
}
__device__ __forceinline__ void mma_bf16(float* d, const uint32_t* a, const uint32_t* b) {
    asm volatile("mma.sync.aligned.m16n8k16.row.col.f32.bf16.bf16.f32 "
                 "{%0,%1,%2,%3},{%4,%5,%6,%7},{%8,%9},{%0,%1,%2,%3};"
                 : "+f"(d[0]), "+f"(d[1]), "+f"(d[2]), "+f"(d[3])
                 : "r"(a[0]), "r"(a[1]), "r"(a[2]), "r"(a[3]), "r"(b[0]), "r"(b[1]));
}
__device__ __forceinline__ void cp_async16(uint32_t dst, const void* src) {
    asm volatile("cp.async.cg.shared.global [%0], [%1], 16;" :: "r"(dst), "l"(src));
}
#define CP_COMMIT() asm volatile("cp.async.commit_group;" ::: "memory")
#define CP_WAIT(n)  asm volatile("cp.async.wait_group %0;" :: "n"(n) : "memory")

// ---------------------------------------------------------------------------
// Split fp32 -> bf16 hi + bf16 lo
// ---------------------------------------------------------------------------
__global__ void split_f32(const float* __restrict__ in, __nv_bfloat16* __restrict__ hi,
                          __nv_bfloat16* __restrict__ lo, int n4)
{
    int i = blockIdx.x * blockDim.x + threadIdx.x;
    if (i >= n4) return;
    float4 v = ((const float4*)in)[i];
    __nv_bfloat16 h0 = __float2bfloat16(v.x);
    __nv_bfloat16 h1 = __float2bfloat16(v.y);
    __nv_bfloat16 h2 = __float2bfloat16(v.z);
    __nv_bfloat16 h3 = __float2bfloat16(v.w);
    __nv_bfloat16 l0 = __float2bfloat16(v.x - __bfloat162float(h0));
    __nv_bfloat16 l1 = __float2bfloat16(v.y - __bfloat162float(h1));
    __nv_bfloat16 l2 = __float2bfloat16(v.z - __bfloat162float(h2));
    __nv_bfloat16 l3 = __float2bfloat16(v.w - __bfloat162float(h3));
    ((__nv_bfloat162*)hi)[2*i]   = __halves2bfloat162(h0, h1);
    ((__nv_bfloat162*)hi)[2*i+1] = __halves2bfloat162(h2, h3);
    ((__nv_bfloat162*)lo)[2*i]   = __halves2bfloat162(l0, l1);
    ((__nv_bfloat162*)lo)[2*i+1] = __halves2bfloat162(l2, l3);
}

// ---------------------------------------------------------------------------
// HMMA split-bf16 GEMM: out[m][n] = sum_k X[m][k]*W[n][k]
// 128x128 block, 8 warps (warp tile 64x32), BK=32, cp.async double buffer.
// Smem tiles: 128 rows x 32 bf16, row stride 80B (conflict-free ldmatrix).
// MODE 0: scatter to [b][h][s][dh]; MODE 1: row-major + bias.
// ---------------------------------------------------------------------------
#define TILE_B   10240          // 128 * 80
#define STAGE_B  40960          // 4 tiles
#define GEMM_SMEM (2*STAGE_B)   // 81920

template<int MODE>
__global__ __launch_bounds__(256)
void gemm_mma(const __nv_bfloat16* __restrict__ Xh, const __nv_bfloat16* __restrict__ Xl,
              const __nv_bfloat16* __restrict__ Wh, const __nv_bfloat16* __restrict__ Wl,
              const float* __restrict__ bias, float* __restrict__ out)
{
    extern __shared__ __align__(128) char smem[];
    const int tid  = threadIdx.x;
    const int lane = tid & 31;
    const int wid  = tid >> 5;
    const int m0 = blockIdx.y * 128;
    const int n0 = blockIdx.x * 128;
    const int wm = (wid & 1) * 64;     // 2 warps along M
    const int wn = (wid >> 1) * 32;    // 4 warps along N
    const uint32_t sb = smem_u32(smem);

    // per-lane ldmatrix offsets (bytes, within a tile)
    const uint32_t aOff = (uint32_t)((lane & 15) * 80 + (lane >> 4) * 16);
    const uint32_t bOff = (uint32_t)(((lane & 7) + (lane >> 4) * 8) * 80 + ((lane >> 3) & 1) * 16);

    float acc[4][4][4];
#pragma unroll
    for (int i = 0; i < 4; i++)
#pragma unroll
        for (int j = 0; j < 4; j++)
#pragma unroll
            for (int q = 0; q < 4; q++) acc[i][j][q] = 0.f;

    const int row_a = ((tid & 255) >> 2);   // helper below uses explicit compute

    // ---- stage loader: 4 tiles x 512 chunks of 16B, 8 cp.async per thread ----
    auto issue_stage = [&](int c) {
        const uint32_t stage = sb + (uint32_t)(c & 1) * STAGE_B;
        const int kt = c * 32;
#pragma unroll
        for (int i = 0; i < 8; i++) {
            const int tileI = i >> 1;                    // 0..3
            const int w = (i & 1) * 256 + tid;           // 0..511 within tile
            const int row = w >> 2;
            const int ch  = w & 3;
            const __nv_bfloat16* g;
            if (tileI == 0)      g = Xh + (size_t)(m0 + row) * D_ + kt + ch * 8;
            else if (tileI == 1) g = Xl + (size_t)(m0 + row) * D_ + kt + ch * 8;
            else if (tileI == 2) g = Wh + (size_t)(n0 + row) * D_ + kt + ch * 8;
            else                 g = Wl + (size_t)(n0 + row) * D_ + kt + ch * 8;
            cp_async16(stage + (uint32_t)(tileI * TILE_B + row * 80 + ch * 16), g);
        }
        CP_COMMIT();
    };
    (void)row_a;

    issue_stage(0);

    for (int c = 0; c < D_ / 32; ++c) {
        if (c + 1 < D_ / 32) { issue_stage(c + 1); CP_WAIT(1); }
        else                 { CP_WAIT(0); }
        __syncthreads();

        const uint32_t st  = sb + (uint32_t)(c & 1) * STAGE_B;
        const uint32_t aHi = st + 0 * TILE_B + (uint32_t)wm * 80 + aOff;
        const uint32_t aLo = st + 1 * TILE_B + (uint32_t)wm * 80 + aOff;
        const uint32_t bHi = st + 2 * TILE_B + (uint32_t)wn * 80 + bOff;
        const uint32_t bLo = st + 3 * TILE_B + (uint32_t)wn * 80 + bOff;

#pragma unroll
        for (int ks = 0; ks < 2; ks++) {
            const uint32_t ka = (uint32_t)ks * 32;
            uint32_t ah[4][4], bh[2][4];
#pragma unroll
            for (int mt = 0; mt < 4; mt++) ldsm4(aHi + (uint32_t)mt * (16 * 80) + ka, ah[mt]);
#pragma unroll
            for (int p = 0; p < 2; p++)    ldsm4(bHi + (uint32_t)p * (16 * 80) + ka, bh[p]);
#pragma unroll
            for (int mt = 0; mt < 4; mt++)
#pragma unroll
                for (int nt = 0; nt < 4; nt++)
                    mma_bf16(acc[mt][nt], ah[mt], &bh[nt >> 1][(nt & 1) * 2]);

            uint32_t bl[2][4];
#pragma unroll
            for (int p = 0; p < 2; p++)    ldsm4(bLo + (uint32_t)p * (16 * 80) + ka, bl[p]);
#pragma unroll
            for (int mt = 0; mt < 4; mt++)
#pragma unroll
                for (int nt = 0; nt < 4; nt++)
                    mma_bf16(acc[mt][nt], ah[mt], &bl[nt >> 1][(nt & 1) * 2]);

            uint32_t al[4][4];
#pragma unroll
            for (int mt = 0; mt < 4; mt++) ldsm4(aLo + (uint32_t)mt * (16 * 80) + ka, al[mt]);
#pragma unroll
            for (int mt = 0; mt < 4; mt++)
#pragma unroll
                for (int nt = 0; nt < 4; nt++)
                    mma_bf16(acc[mt][nt], al[mt], &bh[nt >> 1][(nt & 1) * 2]);
        }
        __syncthreads();
    }

    // ---- epilogue: direct STG.64 per fragment ----
    const int g = lane >> 2;
    const int t = lane & 3;
#pragma unroll
    for (int mt = 0; mt < 4; mt++) {
        const int r0 = m0 + wm + mt * 16 + g;
        const int r1 = r0 + 8;
#pragma unroll
        for (int nt = 0; nt < 4; nt++) {
            const int col = n0 + wn + nt * 8 + t * 2;
            float2 v0 = make_float2(acc[mt][nt][0], acc[mt][nt][1]);
            float2 v1 = make_float2(acc[mt][nt][2], acc[mt][nt][3]);
            if (MODE == 0) {
                const int h = col >> 6, d = col & 63;
                const int b0i = r0 >> 11, s0 = r0 & 2047;
                const int b1i = r1 >> 11, s1 = r1 & 2047;
                *(float2*)(out + (((size_t)(b0i * H_ + h) * S_ + s0) * DH_ + d)) = v0;
                *(float2*)(out + (((size_t)(b1i * H_ + h) * S_ + s1) * DH_ + d)) = v1;
            } else {
                float2 bv = *(const float2*)(bias + col);
                v0.x += bv.x; v0.y += bv.y;
                v1.x += bv.x; v1.y += bv.y;
                *(float2*)(out + (size_t)r0 * D_ + col) = v0;
                *(float2*)(out + (size_t)r1 * D_ + col) = v1;
            }
        }
    }
}

// ---------------------------------------------------------------------------
// Flash attention, fp32 (unchanged — known good)
// ---------------------------------------------------------------------------
__global__ __launch_bounds__(256)
void attn_kernel(const float* __restrict__ Q, const float* __restrict__ K,
                 const float* __restrict__ V, float* __restrict__ A)
{
    __shared__ float Qs[64 * 64];
    __shared__ float KPs[64 * 64];
    __shared__ float Vs[64 * 64];

    const int bh = blockIdx.y;
    const int q0 = blockIdx.x * 64;
    const float* Qp = Q + (size_t)bh * S_ * DH_;
    const float* Kp = K + (size_t)bh * S_ * DH_;
    const float* Vp = V + (size_t)bh * S_ * DH_;

    const int tid = threadIdx.x;
    const int tx = tid & 15;
    const int ty = tid >> 4;
    const int lr = tid >> 2;
    const int lc = (tid & 3) * 16;

#pragma unroll
    for (int u = 0; u < 4; u++) {
        float4 v = *(const float4*)(Qp + (q0 + lr) * DH_ + lc + u * 4);
        Qs[(lc + u * 4 + 0) * 64 + lr] = v.x * SCALE_;
        Qs[(lc + u * 4 + 1) * 64 + lr] = v.y * SCALE_;
        Qs[(lc + u * 4 + 2) * 64 + lr] = v.z * SCALE_;
        Qs[(lc + u * 4 + 3) * 64 + lr] = v.w * SCALE_;
    }

    float m_old[4], l[4], o[4][4];
#pragma unroll
    for (int i = 0; i < 4; i++) {
        m_old[i] = -3.0e38f; l[i] = 0.f;
#pragma unroll
        for (int j = 0; j < 4; j++) o[i][j] = 0.f;
    }

    for (int kt = 0; kt < S_; kt += 64) {
        __syncthreads();
#pragma unroll
        for (int u = 0; u < 4; u++) {
            float4 kv = *(const float4*)(Kp + (kt + lr) * DH_ + lc + u * 4);
            KPs[(lc + u * 4 + 0) * 64 + lr] = kv.x;
            KPs[(lc + u * 4 + 1) * 64 + lr] = kv.y;
            KPs[(lc + u * 4 + 2) * 64 + lr] = kv.z;
            KPs[(lc + u * 4 + 3) * 64 + lr] = kv.w;
            float4 vv = *(const float4*)(Vp + (kt + lr) * DH_ + lc + u * 4);
            *(float4*)&Vs[lr * 64 + lc + u * 4] = vv;
        }
        __syncthreads();

        float s[4][4];
#pragma unroll
        for (int i = 0; i < 4; i++)
#pragma unroll
            for (int j = 0; j < 4; j++) s[i][j] = 0.f;
#pragma unroll 16
        for (int d = 0; d < 64; d++) {
            float4 a = *(const float4*)&Qs[d * 64 + ty * 4];
            float4 b = *(const float4*)&KPs[d * 64 + tx * 4];
            s[0][0] += a.x * b.x; s[0][1] += a.x * b.y; s[0][2] += a.x * b.z; s[0][3] += a.x * b.w;
            s[1][0] += a.y * b.x; s[1][1] += a.y * b.y; s[1][2] += a.y * b.z; s[1][3] += a.y * b.w;
            s[2][0] += a.z * b.x; s[2][1] += a.z * b.y; s[2][2] += a.z * b.z; s[2][3] += a.z * b.w;
            s[3][0] += a.w * b.x; s[3][1] += a.w * b.y; s[3][2] += a.w * b.z; s[3][3] += a.w * b.w;
        }

#pragma unroll
        for (int i = 0; i < 4; i++) {
            float mt = fmaxf(fmaxf(s[i][0], s[i][1]), fmaxf(s[i][2], s[i][3]));
            mt = fmaxf(mt, __shfl_xor_sync(0xffffffffu, mt, 1));
            mt = fmaxf(mt, __shfl_xor_sync(0xffffffffu, mt, 2));
            mt = fmaxf(mt, __shfl_xor_sync(0xffffffffu, mt, 4));
            mt = fmaxf(mt, __shfl_xor_sync(0xffffffffu, mt, 8));
            float mn = fmaxf(m_old[i], mt);
            float corr = __expf(m_old[i] - mn);
            float p0 = __expf(s[i][0] - mn);
            float p1 = __expf(s[i][1] - mn);
            float p2 = __expf(s[i][2] - mn);
            float p3 = __expf(s[i][3] - mn);
            float ls = (p0 + p1) + (p2 + p3);
            ls += __shfl_xor_sync(0xffffffffu, ls, 1);
            ls += __shfl_xor_sync(0xffffffffu, ls, 2);
            ls += __shfl_xor_sync(0xffffffffu, ls, 4);
            ls += __shfl_xor_sync(0xffffffffu, ls, 8);
            l[i] = l[i] * corr + ls;
            o[i][0] *= corr; o[i][1] *= corr; o[i][2] *= corr; o[i][3] *= corr;
            m_old[i] = mn;
            s[i][0] = p0; s[i][1] = p1; s[i][2] = p2; s[i][3] = p3;
        }

        __syncthreads();
#pragma unroll
        for (int j = 0; j < 4; j++) {
            int kcol = tx * 4 + j;
            int base = kcol * 64 + ((ty * 4) ^ ((kcol & 15) << 2));
#pragma unroll
            for (int i = 0; i < 4; i++)
                KPs[base + i] = s[i][j];
        }
        __syncthreads();

#pragma unroll 16
        for (int k = 0; k < 64; k++) {
            float4 p = *(const float4*)&KPs[k * 64 + ((ty * 4) ^ ((k & 15) << 2))];
            float4 v = *(const float4*)&Vs[k * 64 + tx * 4];
            o[0][0] += p.x * v.x; o[0][1] += p.x * v.y; o[0][2] += p.x * v.z; o[0][3] += p.x * v.w;
            o[1][0] += p.y * v.x; o[1][1] += p.y * v.y; o[1][2] += p.y * v.z; o[1][3] += p.y * v.w;
            o[2][0] += p.z * v.x; o[2][1] += p.z * v.y; o[2][2] += p.z * v.z; o[2][3] += p.z * v.w;
            o[3][0] += p.w * v.x; o[3][1] += p.w * v.y; o[3][2] += p.w * v.z; o[3][3] += p.w * v.w;
        }
    }

    const int b = bh >> 4;
    const int h = bh & 15;
#pragma unroll
    for (int i = 0; i < 4; i++) {
        float inv = 1.f / l[i];
        int s_idx = q0 + ty * 4 + i;
        float4 v = make_float4(o[i][0] * inv, o[i][1] * inv, o[i][2] * inv, o[i][3] * inv);
        *(float4*)(A + ((size_t)(b * S_ + s_idx) * D_ + h * DH_ + tx * 4)) = v;
    }
}

// ---------------------------------------------------------------------------
extern "C" void kernel_launch(void* const* d_in, const int* in_sizes, int n_in,
                              void* d_out, int out_size)
{
    const float* x  = (const float*)d_in[0];
    const float* Wq = (const float*)d_in[1];
    const float* Wk = (const float*)d_in[2];
    const float* Wv = (const float*)d_in[3];
    const float* Wo = (const float*)d_in[4];
    const float* bo = (const float*)d_in[5];
    float* out = (float*)d_out;

    float *Qb, *Kb, *Vb, *Ab;
    __nv_bfloat16 *Xh, *Xl, *Wh, *Wl, *Ah, *Al;
    cudaGetSymbolAddress((void**)&Qb, g_Q);
    cudaGetSymbolAddress((void**)&Kb, g_K);
    cudaGetSymbolAddress((void**)&Vb, g_V);
    cudaGetSymbolAddress((void**)&Ab, g_A);
    cudaGetSymbolAddress((void**)&Xh, g_Xh);
    cudaGetSymbolAddress((void**)&Xl, g_Xl);
    cudaGetSymbolAddress((void**)&Wh, g_Wh);
    cudaGetSymbolAddress((void**)&Wl, g_Wl);
    cudaGetSymbolAddress((void**)&Ah, g_Ah);
    cudaGetSymbolAddress((void**)&Al, g_Al);

    static bool attr_set = false;
    if (!attr_set) {
        cudaFuncSetAttribute(gemm_mma<0>, cudaFuncAttributeMaxDynamicSharedMemorySize, GEMM_SMEM);
        cudaFuncSetAttribute(gemm_mma<1>, cudaFuncAttributeMaxDynamicSharedMemorySize, GEMM_SMEM);
        attr_set = true;
    }

    const int nX4 = M_ * D_ / 4;
    const int nW4 = D_ * D_ / 4;
    split_f32<<<(nX4 + 255) / 256, 256>>>(x,  Xh, Xl, nX4);
    split_f32<<<(nW4 + 255) / 256, 256>>>(Wq, Wh + 0 * (size_t)D_ * D_, Wl + 0 * (size_t)D_ * D_, nW4);
    split_f32<<<(nW4 + 255) / 256, 256>>>(Wk, Wh + 1 * (size_t)D_ * D_, Wl + 1 * (size_t)D_ * D_, nW4);
    split_f32<<<(nW4 + 255) / 256, 256>>>(Wv, Wh + 2 * (size_t)D_ * D_, Wl + 2 * (size_t)D_ * D_, nW4);
    split_f32<<<(nW4 + 255) / 256, 256>>>(Wo, Wh + 3 * (size_t)D_ * D_, Wl + 3 * (size_t)D_ * D_, nW4);

    dim3 gg(D_ / 128, M_ / 128);   // (8, 32)
    gemm_mma<0><<<gg, 256, GEMM_SMEM>>>(Xh, Xl, Wh + 0 * (size_t)D_ * D_, Wl + 0 * (size_t)D_ * D_, nullptr, Qb);
    gemm_mma<0><<<gg, 256, GEMM_SMEM>>>(Xh, Xl, Wh + 1 * (size_t)D_ * D_, Wl + 1 * (size_t)D_ * D_, nullptr, Kb);
    gemm_mma<0><<<gg, 256, GEMM_SMEM>>>(Xh, Xl, Wh + 2 * (size_t)D_ * D_, Wl + 2 * (size_t)D_ * D_, nullptr, Vb);

    attn_kernel<<<dim3(S_ / 64, B_ * H_), 256>>>(Qb, Kb, Vb, Ab);

    split_f32<<<(nX4 + 255) / 256, 256>>>(Ab, Ah, Al, nX4);
    gemm_mma<1><<<gg, 256, GEMM_SMEM>>>(Ah, Al, Wh + 3 * (size_t)D_ * D_, Wl + 3 * (size_t)D_ * D_, bo, out);
}

// round 6
// speedup vs baseline: 4.4044x; 2.9228x over previous
#include <cuda_runtime.h>
#include <cuda_bf16.h>
#include <cuda_fp16.h>
#include <stdint.h>
#include <math.h>

// Problem constants
#define B_  2
#define S_  2048
#define D_  1024
#define H_  16
#define DH_ 64
#define M_  (B_*S_)          // 4096
#define SCALE_ 0.125f

// ---------------------------------------------------------------------------
// Scratch (__device__ globals; allocation-free rule)
// ---------------------------------------------------------------------------
static __device__ __half g_Qh[B_*H_*S_*DH_];   // [b][h][s][dh] fp16 (pre-scaled)
static __device__ __half g_Kh[B_*H_*S_*DH_];
static __device__ __half g_Vh[B_*H_*S_*DH_];
static __device__ __nv_bfloat16 g_Xh[M_*D_], g_Xl[M_*D_];
static __device__ __nv_bfloat16 g_Wh[4*D_*D_], g_Wl[4*D_*D_];
static __device__ __nv_bfloat16 g_Ah[M_*D_], g_Al[M_*D_];

// ---------------------------------------------------------------------------
// Base-ISA tensor-core helpers
// ---------------------------------------------------------------------------
__device__ __forceinline__ uint32_t smem_u32(const void* p) {
    uint32_t a;
    asm("{ .reg .u64 t; cvta.to.shared.u64 t, %1; cvt.u32.u64 %0, t; }" : "=r"(a) : "l"(p));
    return a;
}
__device__ __forceinline__ uint32_t h2_u32(__half2 h) {
    union { __half2 h; uint32_t u; } cvt;
    cvt.h = h;
    return cvt.u;
}
__device__ __forceinline__ void ldsm4(uint32_t addr, uint32_t* r) {
    asm volatile("ldmatrix.sync.aligned.m8n8.x4.shared.b16 {%0,%1,%2,%3}, [%4];"
                 : "=r"(r[0]), "=r"(r[1]), "=r"(r[2]), "=r"(r[3]) : "r"(addr));
}
__device__ __forceinline__ void ldsm4t(uint32_t addr, uint32_t* r) {
    asm volatile("ldmatrix.sync.aligned.m8n8.x4.trans.shared.b16 {%0,%1,%2,%3}, [%4];"
                 : "=r"(r[0]), "=r"(r[1]), "=r"(r[2]), "=r"(r[3]) : "r"(addr));
}
__device__ __forceinline__ void mma_bf16(float* d, const uint32_t* a, const uint32_t* b) {
    asm volatile("mma.sync.aligned.m16n8k16.row.col.f32.bf16.bf16.f32 "
                 "{%0,%1,%2,%3},{%4,%5,%6,%7},{%8,%9},{%0,%1,%2,%3};"
                 : "+f"(d[0]), "+f"(d[1]), "+f"(d[2]), "+f"(d[3])
                 : "r"(a[0]), "r"(a[1]), "r"(a[2]), "r"(a[3]), "r"(b[0]), "r"(b[1]));
}
__device__ __forceinline__ void mma_f16(float* d, const uint32_t* a, const uint32_t* b) {
    asm volatile("mma.sync.aligned.m16n8k16.row.col.f32.f16.f16.f32 "
                 "{%0,%1,%2,%3},{%4,%5,%6,%7},{%8,%9},{%0,%1,%2,%3};"
                 : "+f"(d[0]), "+f"(d[1]), "+f"(d[2]), "+f"(d[3])
                 : "r"(a[0]), "r"(a[1]), "r"(a[2]), "r"(a[3]), "r"(b[0]), "r"(b[1]));
}
__device__ __forceinline__ void cp_async16(uint32_t dst, const void* src) {
    asm volatile("cp.async.cg.shared.global [%0], [%1], 16;" :: "r"(dst), "l"(src));
}
#define CP_COMMIT() asm volatile("cp.async.commit_group;" ::: "memory")
#define CP_WAIT(n)  asm volatile("cp.async.wait_group %0;" :: "n"(n) : "memory")

// ---------------------------------------------------------------------------
// Split fp32 -> bf16 hi + bf16 lo
// ---------------------------------------------------------------------------
__global__ void split_f32(const float* __restrict__ in, __nv_bfloat16* __restrict__ hi,
                          __nv_bfloat16* __restrict__ lo, int n4)
{
    int i = blockIdx.x * blockDim.x + threadIdx.x;
    if (i >= n4) return;
    float4 v = ((const float4*)in)[i];
    __nv_bfloat16 h0 = __float2bfloat16(v.x);
    __nv_bfloat16 h1 = __float2bfloat16(v.y);
    __nv_bfloat16 h2 = __float2bfloat16(v.z);
    __nv_bfloat16 h3 = __float2bfloat16(v.w);
    __nv_bfloat16 l0 = __float2bfloat16(v.x - __bfloat162float(h0));
    __nv_bfloat16 l1 = __float2bfloat16(v.y - __bfloat162float(h1));
    __nv_bfloat16 l2 = __float2bfloat16(v.z - __bfloat162float(h2));
    __nv_bfloat16 l3 = __float2bfloat16(v.w - __bfloat162float(h3));
    ((__nv_bfloat162*)hi)[2*i]   = __halves2bfloat162(h0, h1);
    ((__nv_bfloat162*)hi)[2*i+1] = __halves2bfloat162(h2, h3);
    ((__nv_bfloat162*)lo)[2*i]   = __halves2bfloat162(l0, l1);
    ((__nv_bfloat162*)lo)[2*i+1] = __halves2bfloat162(l2, l3);
}

// ---------------------------------------------------------------------------
// HMMA split-bf16 GEMM: out[m][n] = sum_k X[m][k]*W[n][k]
// MODE 0: fp16 scatter to [b][h][s][dh] (optionally scaled)
// MODE 1: fp32 row-major + bias
// ---------------------------------------------------------------------------
#define TILE_B   10240          // 128 * 80
#define STAGE_B  40960          // 4 tiles
#define GEMM_SMEM (2*STAGE_B)   // 81920

template<int MODE>
__global__ __launch_bounds__(256)
void gemm_mma(const __nv_bfloat16* __restrict__ Xh, const __nv_bfloat16* __restrict__ Xl,
              const __nv_bfloat16* __restrict__ Wh, const __nv_bfloat16* __restrict__ Wl,
              const float* __restrict__ bias, float* __restrict__ outF,
              __half* __restrict__ outH, float scale)
{
    extern __shared__ __align__(128) char smem[];
    const int tid  = threadIdx.x;
    const int lane = tid & 31;
    const int wid  = tid >> 5;
    const int m0 = blockIdx.y * 128;
    const int n0 = blockIdx.x * 128;
    const int wm = (wid & 1) * 64;
    const int wn = (wid >> 1) * 32;
    const uint32_t sb = smem_u32(smem);

    const uint32_t aOff = (uint32_t)((lane & 15) * 80 + (lane >> 4) * 16);
    const uint32_t bOff = (uint32_t)(((lane & 7) + (lane >> 4) * 8) * 80 + ((lane >> 3) & 1) * 16);

    float acc[4][4][4];
#pragma unroll
    for (int i = 0; i < 4; i++)
#pragma unroll
        for (int j = 0; j < 4; j++)
#pragma unroll
            for (int q = 0; q < 4; q++) acc[i][j][q] = 0.f;

    auto issue_stage = [&](int c) {
        const uint32_t stage = sb + (uint32_t)(c & 1) * STAGE_B;
        const int kt = c * 32;
#pragma unroll
        for (int i = 0; i < 8; i++) {
            const int tileI = i >> 1;
            const int w = (i & 1) * 256 + tid;
            const int row = w >> 2;
            const int ch  = w & 3;
            const __nv_bfloat16* g;
            if (tileI == 0)      g = Xh + (size_t)(m0 + row) * D_ + kt + ch * 8;
            else if (tileI == 1) g = Xl + (size_t)(m0 + row) * D_ + kt + ch * 8;
            else if (tileI == 2) g = Wh + (size_t)(n0 + row) * D_ + kt + ch * 8;
            else                 g = Wl + (size_t)(n0 + row) * D_ + kt + ch * 8;
            cp_async16(stage + (uint32_t)(tileI * TILE_B + row * 80 + ch * 16), g);
        }
        CP_COMMIT();
    };

    issue_stage(0);

    for (int c = 0; c < D_ / 32; ++c) {
        if (c + 1 < D_ / 32) { issue_stage(c + 1); CP_WAIT(1); }
        else                 { CP_WAIT(0); }
        __syncthreads();

        const uint32_t st  = sb + (uint32_t)(c & 1) * STAGE_B;
        const uint32_t aHi = st + 0 * TILE_B + (uint32_t)wm * 80 + aOff;
        const uint32_t aLo = st + 1 * TILE_B + (uint32_t)wm * 80 + aOff;
        const uint32_t bHi = st + 2 * TILE_B + (uint32_t)wn * 80 + bOff;
        const uint32_t bLo = st + 3 * TILE_B + (uint32_t)wn * 80 + bOff;

#pragma unroll
        for (int ks = 0; ks < 2; ks++) {
            const uint32_t ka = (uint32_t)ks * 32;
            uint32_t ah[4][4], bh[2][4];
#pragma unroll
            for (int mt = 0; mt < 4; mt++) ldsm4(aHi + (uint32_t)mt * (16 * 80) + ka, ah[mt]);
#pragma unroll
            for (int p = 0; p < 2; p++)    ldsm4(bHi + (uint32_t)p * (16 * 80) + ka, bh[p]);
#pragma unroll
            for (int mt = 0; mt < 4; mt++)
#pragma unroll
                for (int nt = 0; nt < 4; nt++)
                    mma_bf16(acc[mt][nt], ah[mt], &bh[nt >> 1][(nt & 1) * 2]);

            uint32_t bl[2][4];
#pragma unroll
            for (int p = 0; p < 2; p++)    ldsm4(bLo + (uint32_t)p * (16 * 80) + ka, bl[p]);
#pragma unroll
            for (int mt = 0; mt < 4; mt++)
#pragma unroll
                for (int nt = 0; nt < 4; nt++)
                    mma_bf16(acc[mt][nt], ah[mt], &bl[nt >> 1][(nt & 1) * 2]);

            uint32_t al[4][4];
#pragma unroll
            for (int mt = 0; mt < 4; mt++) ldsm4(aLo + (uint32_t)mt * (16 * 80) + ka, al[mt]);
#pragma unroll
            for (int mt = 0; mt < 4; mt++)
#pragma unroll
                for (int nt = 0; nt < 4; nt++)
                    mma_bf16(acc[mt][nt], al[mt], &bh[nt >> 1][(nt & 1) * 2]);
        }
        __syncthreads();
    }

    const int g = lane >> 2;
    const int t = lane & 3;
#pragma unroll
    for (int mt = 0; mt < 4; mt++) {
        const int r0 = m0 + wm + mt * 16 + g;
        const int r1 = r0 + 8;
#pragma unroll
        for (int nt = 0; nt < 4; nt++) {
            const int col = n0 + wn + nt * 8 + t * 2;
            if (MODE == 0) {
                const int h = col >> 6, d = col & 63;
                const int b0i = r0 >> 11, s0 = r0 & 2047;
                const int b1i = r1 >> 11, s1 = r1 & 2047;
                __half2 v0 = __floats2half2_rn(acc[mt][nt][0] * scale, acc[mt][nt][1] * scale);
                __half2 v1 = __floats2half2_rn(acc[mt][nt][2] * scale, acc[mt][nt][3] * scale);
                *(__half2*)(outH + (((size_t)(b0i * H_ + h) * S_ + s0) * DH_ + d)) = v0;
                *(__half2*)(outH + (((size_t)(b1i * H_ + h) * S_ + s1) * DH_ + d)) = v1;
            } else {
                float2 bv = *(const float2*)(bias + col);
                float2 v0 = make_float2(acc[mt][nt][0] + bv.x, acc[mt][nt][1] + bv.y);
                float2 v1 = make_float2(acc[mt][nt][2] + bv.x, acc[mt][nt][3] + bv.y);
                *(float2*)(outF + (size_t)r0 * D_ + col) = v0;
                *(float2*)(outF + (size_t)r1 * D_ + col) = v1;
            }
        }
    }
}

// ---------------------------------------------------------------------------
// HMMA flash attention (fp16 QK^T and PV, fp32 softmax/accum)
// One CTA = one (b,h) x 128 queries. 8 warps x m16. 64-key blocks, double buf.
// Smem rows: 64 halves + pad -> 144B stride (conflict-free ldmatrix).
// Epilogue writes split-bf16 Ah/Al directly.
// ---------------------------------------------------------------------------
#define KSTR      144
#define Q_BYTES   (128*KSTR)           // 18432
#define KV_HALF   (64*KSTR)            // 9216 (one of K or V)
#define KV_STAGE  (2*KV_HALF)          // 18432
#define ATTN_SMEM (Q_BYTES + 2*KV_STAGE)  // 55296

__global__ __launch_bounds__(256)
void attn_mma(const __half* __restrict__ Q, const __half* __restrict__ K,
              const __half* __restrict__ V, __nv_bfloat16* __restrict__ Ah,
              __nv_bfloat16* __restrict__ Al)
{
    extern __shared__ __align__(128) char smem[];
    const uint32_t sb = smem_u32(smem);
    const int tid  = threadIdx.x;
    const int lane = tid & 31;
    const int wid  = tid >> 5;
    const int bh = blockIdx.y;
    const int q0 = blockIdx.x * 128;
    const __half* Qp = Q + (size_t)bh * S_ * DH_;
    const __half* Kp = K + (size_t)bh * S_ * DH_;
    const __half* Vp = V + (size_t)bh * S_ * DH_;

    const uint32_t bOff = (uint32_t)(((lane & 7) + (lane >> 4) * 8) * KSTR + ((lane >> 3) & 1) * 16);
    const uint32_t vOff = (uint32_t)((lane & 15) * KSTR + (lane >> 4) * 16);

    // ---- issue Q tile loads (group 0) ----
#pragma unroll
    for (int i = 0; i < 4; i++) {
        int idx = tid + i * 256;       // 0..1023
        int row = idx >> 3, ch = idx & 7;
        cp_async16(sb + (uint32_t)(row * KSTR + ch * 16),
                   Qp + (size_t)(q0 + row) * DH_ + ch * 8);
    }
    CP_COMMIT();

    auto issue_kv = [&](int c) {
        const uint32_t st = sb + Q_BYTES + (uint32_t)(c & 1) * KV_STAGE;
        const int kt = c * 64;
#pragma unroll
        for (int i = 0; i < 4; i++) {
            int idx = tid + i * 256;   // 0..1023 ; <512 K, >=512 V
            int loc = idx & 511;
            int row = loc >> 3, ch = loc & 7;
            const __half* src = (idx < 512) ? (Kp + (size_t)(kt + row) * DH_ + ch * 8)
                                            : (Vp + (size_t)(kt + row) * DH_ + ch * 8);
            uint32_t dst = st + (uint32_t)((idx < 512 ? 0 : KV_HALF) + row * KSTR + ch * 16);
            cp_async16(dst, src);
        }
        CP_COMMIT();
    };

    issue_kv(0);
    CP_WAIT(1);            // Q group done
    __syncthreads();

    // ---- Q fragments (held in regs for whole kernel) ----
    uint32_t qf[4][4];
    const uint32_t qAddr = sb + (uint32_t)((wid * 16 + (lane & 15)) * KSTR + (lane >> 4) * 16);
#pragma unroll
    for (int kf = 0; kf < 4; kf++) ldsm4(qAddr + (uint32_t)kf * 32, qf[kf]);

    float of[8][4];
#pragma unroll
    for (int t = 0; t < 8; t++)
#pragma unroll
        for (int q = 0; q < 4; q++) of[t][q] = 0.f;
    float m_lo = -1e30f, m_hi = -1e30f, l_lo = 0.f, l_hi = 0.f;

    for (int c = 0; c < S_ / 64; ++c) {
        if (c + 1 < S_ / 64) { issue_kv(c + 1); CP_WAIT(1); }
        else                 { CP_WAIT(0); }
        __syncthreads();

        const uint32_t Kst = sb + Q_BYTES + (uint32_t)(c & 1) * KV_STAGE;
        const uint32_t Vst = Kst + KV_HALF;

        // ---- S = Q K^T ----
        float sf[8][4];
#pragma unroll
        for (int t = 0; t < 8; t++)
#pragma unroll
            for (int q = 0; q < 4; q++) sf[t][q] = 0.f;
#pragma unroll
        for (int kf = 0; kf < 4; kf++) {
            uint32_t kb[4][4];
#pragma unroll
            for (int kg = 0; kg < 4; kg++)
                ldsm4(Kst + (uint32_t)(kg * 16 * KSTR) + (uint32_t)kf * 32 + bOff, kb[kg]);
#pragma unroll
            for (int kg = 0; kg < 4; kg++) {
                mma_f16(sf[2 * kg],     qf[kf], &kb[kg][0]);
                mma_f16(sf[2 * kg + 1], qf[kf], &kb[kg][2]);
            }
        }

        // ---- online softmax ----
        float mt_lo = -1e30f, mt_hi = -1e30f;
#pragma unroll
        for (int t = 0; t < 8; t++) {
            mt_lo = fmaxf(mt_lo, fmaxf(sf[t][0], sf[t][1]));
            mt_hi = fmaxf(mt_hi, fmaxf(sf[t][2], sf[t][3]));
        }
        mt_lo = fmaxf(mt_lo, __shfl_xor_sync(0xffffffffu, mt_lo, 1));
        mt_lo = fmaxf(mt_lo, __shfl_xor_sync(0xffffffffu, mt_lo, 2));
        mt_hi = fmaxf(mt_hi, __shfl_xor_sync(0xffffffffu, mt_hi, 1));
        mt_hi = fmaxf(mt_hi, __shfl_xor_sync(0xffffffffu, mt_hi, 2));
        const float mn_lo = fmaxf(m_lo, mt_lo);
        const float mn_hi = fmaxf(m_hi, mt_hi);
        const float corr_lo = __expf(m_lo - mn_lo);
        const float corr_hi = __expf(m_hi - mn_hi);
        m_lo = mn_lo; m_hi = mn_hi;

        float ls_lo = 0.f, ls_hi = 0.f;
#pragma unroll
        for (int t = 0; t < 8; t++) {
            sf[t][0] = __expf(sf[t][0] - mn_lo);
            sf[t][1] = __expf(sf[t][1] - mn_lo);
            sf[t][2] = __expf(sf[t][2] - mn_hi);
            sf[t][3] = __expf(sf[t][3] - mn_hi);
            ls_lo += sf[t][0] + sf[t][1];
            ls_hi += sf[t][2] + sf[t][3];
        }
        l_lo = l_lo * corr_lo + ls_lo;
        l_hi = l_hi * corr_hi + ls_hi;
#pragma unroll
        for (int t = 0; t < 8; t++) {
            of[t][0] *= corr_lo; of[t][1] *= corr_lo;
            of[t][2] *= corr_hi; of[t][3] *= corr_hi;
        }

        // ---- pack P as fp16 A-fragments ----
        uint32_t pa[4][4];
#pragma unroll
        for (int kf = 0; kf < 4; kf++) {
            pa[kf][0] = h2_u32(__floats2half2_rn(sf[2 * kf][0],     sf[2 * kf][1]));
            pa[kf][1] = h2_u32(__floats2half2_rn(sf[2 * kf][2],     sf[2 * kf][3]));
            pa[kf][2] = h2_u32(__floats2half2_rn(sf[2 * kf + 1][0], sf[2 * kf + 1][1]));
            pa[kf][3] = h2_u32(__floats2half2_rn(sf[2 * kf + 1][2], sf[2 * kf + 1][3]));
        }

        // ---- O += P V ----
#pragma unroll
        for (int kf = 0; kf < 4; kf++) {
            uint32_t vb[4][4];
#pragma unroll
            for (int ng = 0; ng < 4; ng++)
                ldsm4t(Vst + (uint32_t)(kf * 16 * KSTR) + (uint32_t)(ng * 32) + vOff, vb[ng]);
#pragma unroll
            for (int ng = 0; ng < 4; ng++) {
                mma_f16(of[2 * ng],     pa[kf], &vb[ng][0]);
                mma_f16(of[2 * ng + 1], pa[kf], &vb[ng][2]);
            }
        }
        __syncthreads();   // all warps done with this stage before next issue
    }

    // ---- epilogue: reduce l across quad, divide, split-bf16 store ----
    l_lo += __shfl_xor_sync(0xffffffffu, l_lo, 1);
    l_lo += __shfl_xor_sync(0xffffffffu, l_lo, 2);
    l_hi += __shfl_xor_sync(0xffffffffu, l_hi, 1);
    l_hi += __shfl_xor_sync(0xffffffffu, l_hi, 2);
    const float inv_lo = 1.f / l_lo;
    const float inv_hi = 1.f / l_hi;

    const int b = bh >> 4;
    const int h = bh & 15;
    const int row0 = q0 + wid * 16 + (lane >> 2);
    const int row1 = row0 + 8;
#pragma unroll
    for (int t = 0; t < 8; t++) {
        const int colG = h * DH_ + t * 8 + (lane & 3) * 2;
        float v0 = of[t][0] * inv_lo, v1 = of[t][1] * inv_lo;
        float v2 = of[t][2] * inv_hi, v3 = of[t][3] * inv_hi;
        __nv_bfloat16 h0 = __float2bfloat16(v0), h1 = __float2bfloat16(v1);
        __nv_bfloat16 h2 = __float2bfloat16(v2), h3 = __float2bfloat16(v3);
        __nv_bfloat16 e0 = __float2bfloat16(v0 - __bfloat162float(h0));
        __nv_bfloat16 e1 = __float2bfloat16(v1 - __bfloat162float(h1));
        __nv_bfloat16 e2 = __float2bfloat16(v2 - __bfloat162float(h2));
        __nv_bfloat16 e3 = __float2bfloat16(v3 - __bfloat162float(h3));
        size_t a0 = (size_t)(b * S_ + row0) * D_ + colG;
        size_t a1 = (size_t)(b * S_ + row1) * D_ + colG;
        *(__nv_bfloat162*)(Ah + a0) = __halves2bfloat162(h0, h1);
        *(__nv_bfloat162*)(Al + a0) = __halves2bfloat162(e0, e1);
        *(__nv_bfloat162*)(Ah + a1) = __halves2bfloat162(h2, h3);
        *(__nv_bfloat162*)(Al + a1) = __halves2bfloat162(e2, e3);
    }
}

// ---------------------------------------------------------------------------
extern "C" void kernel_launch(void* const* d_in, const int* in_sizes, int n_in,
                              void* d_out, int out_size)
{
    const float* x  = (const float*)d_in[0];
    const float* Wq = (const float*)d_in[1];
    const float* Wk = (const float*)d_in[2];
    const float* Wv = (const float*)d_in[3];
    const float* Wo = (const float*)d_in[4];
    const float* bo = (const float*)d_in[5];
    float* out = (float*)d_out;

    __half *Qh, *Kh, *Vh;
    __nv_bfloat16 *Xh, *Xl, *Wh, *Wl, *Ah, *Al;
    cudaGetSymbolAddress((void**)&Qh, g_Qh);
    cudaGetSymbolAddress((void**)&Kh, g_Kh);
    cudaGetSymbolAddress((void**)&Vh, g_Vh);
    cudaGetSymbolAddress((void**)&Xh, g_Xh);
    cudaGetSymbolAddress((void**)&Xl, g_Xl);
    cudaGetSymbolAddress((void**)&Wh, g_Wh);
    cudaGetSymbolAddress((void**)&Wl, g_Wl);
    cudaGetSymbolAddress((void**)&Ah, g_Ah);
    cudaGetSymbolAddress((void**)&Al, g_Al);

    static bool attr_set = false;
    if (!attr_set) {
        cudaFuncSetAttribute(gemm_mma<0>, cudaFuncAttributeMaxDynamicSharedMemorySize, GEMM_SMEM);
        cudaFuncSetAttribute(gemm_mma<1>, cudaFuncAttributeMaxDynamicSharedMemorySize, GEMM_SMEM);
        cudaFuncSetAttribute(attn_mma,    cudaFuncAttributeMaxDynamicSharedMemorySize, ATTN_SMEM);
        attr_set = true;
    }

    const int nX4 = M_ * D_ / 4;
    const int nW4 = D_ * D_ / 4;
    split_f32<<<(nX4 + 255) / 256, 256>>>(x,  Xh, Xl, nX4);
    split_f32<<<(nW4 + 255) / 256, 256>>>(Wq, Wh + 0 * (size_t)D_ * D_, Wl + 0 * (size_t)D_ * D_, nW4);
    split_f32<<<(nW4 + 255) / 256, 256>>>(Wk, Wh + 1 * (size_t)D_ * D_, Wl + 1 * (size_t)D_ * D_, nW4);
    split_f32<<<(nW4 + 255) / 256, 256>>>(Wv, Wh + 2 * (size_t)D_ * D_, Wl + 2 * (size_t)D_ * D_, nW4);
    split_f32<<<(nW4 + 255) / 256, 256>>>(Wo, Wh + 3 * (size_t)D_ * D_, Wl + 3 * (size_t)D_ * D_, nW4);

    dim3 gg(D_ / 128, M_ / 128);   // (8, 32)
    gemm_mma<0><<<gg, 256, GEMM_SMEM>>>(Xh, Xl, Wh + 0 * (size_t)D_ * D_, Wl + 0 * (size_t)D_ * D_,
                                        nullptr, nullptr, Qh, SCALE_);
    gemm_mma<0><<<gg, 256, GEMM_SMEM>>>(Xh, Xl, Wh + 1 * (size_t)D_ * D_, Wl + 1 * (size_t)D_ * D_,
                                        nullptr, nullptr, Kh, 1.0f);
    gemm_mma<0><<<gg, 256, GEMM_SMEM>>>(Xh, Xl, Wh + 2 * (size_t)D_ * D_, Wl + 2 * (size_t)D_ * D_,
                                        nullptr, nullptr, Vh, 1.0f);

    attn_mma<<<dim3(S_ / 128, B_ * H_), 256, ATTN_SMEM>>>(Qh, Kh, Vh, Ah, Al);

    gemm_mma<1><<<gg, 256, GEMM_SMEM>>>(Ah, Al, Wh + 3 * (size_t)D_ * D_, Wl + 3 * (size_t)D_ * D_,
                                        bo, out, nullptr, 1.0f);
}

// round 7
// speedup vs baseline: 5.4697x; 1.2419x over previous
#include <cuda_runtime.h>
#include <cuda_bf16.h>
#include <cuda_fp16.h>
#include <stdint.h>
#include <math.h>

// Problem constants
#define B_  2
#define S_  2048
#define D_  1024
#define H_  16
#define DH_ 64
#define M_  (B_*S_)          // 4096
#define SCALE_ 0.125f

// ---------------------------------------------------------------------------
// Scratch (__device__ globals; allocation-free rule)
// ---------------------------------------------------------------------------
static __device__ __half g_Qh[B_*H_*S_*DH_];   // [b][h][s][dh] fp16 (pre-scaled)
static __device__ __half g_Kh[B_*H_*S_*DH_];
static __device__ __half g_Vh[B_*H_*S_*DH_];
static __device__ __half g_Xh[M_*D_], g_Xl[M_*D_];   // fp16 split of hidden_states
static __device__ __half g_Wf[4*D_*D_];              // fp16 W: [Wq;Wk;Wv;Wo] stacked
static __device__ __half g_Ah[M_*D_], g_Al[M_*D_];   // fp16 split of attention out

// ---------------------------------------------------------------------------
// Base-ISA tensor-core helpers
// ---------------------------------------------------------------------------
__device__ __forceinline__ uint32_t smem_u32(const void* p) {
    uint32_t a;
    asm("{ .reg .u64 t; cvta.to.shared.u64 t, %1; cvt.u32.u64 %0, t; }" : "=r"(a) : "l"(p));
    return a;
}
__device__ __forceinline__ uint32_t h2_u32(__half2 h) {
    union { __half2 h; uint32_t u; } cvt;
    cvt.h = h;
    return cvt.u;
}
__device__ __forceinline__ void ldsm4(uint32_t addr, uint32_t* r) {
    asm volatile("ldmatrix.sync.aligned.m8n8.x4.shared.b16 {%0,%1,%2,%3}, [%4];"
                 : "=r"(r[0]), "=r"(r[1]), "=r"(r[2]), "=r"(r[3]) : "r"(addr));
}
__device__ __forceinline__ void ldsm4t(uint32_t addr, uint32_t* r) {
    asm volatile("ldmatrix.sync.aligned.m8n8.x4.trans.shared.b16 {%0,%1,%2,%3}, [%4];"
                 : "=r"(r[0]), "=r"(r[1]), "=r"(r[2]), "=r"(r[3]) : "r"(addr));
}
__device__ __forceinline__ void mma_f16(float* d, const uint32_t* a, const uint32_t* b) {
    asm volatile("mma.sync.aligned.m16n8k16.row.col.f32.f16.f16.f32 "
                 "{%0,%1,%2,%3},{%4,%5,%6,%7},{%8,%9},{%0,%1,%2,%3};"
                 : "+f"(d[0]), "+f"(d[1]), "+f"(d[2]), "+f"(d[3])
                 : "r"(a[0]), "r"(a[1]), "r"(a[2]), "r"(a[3]), "r"(b[0]), "r"(b[1]));
}
__device__ __forceinline__ void cp_async16(uint32_t dst, const void* src) {
    asm volatile("cp.async.cg.shared.global [%0], [%1], 16;" :: "r"(dst), "l"(src));
}
#define CP_COMMIT() asm volatile("cp.async.commit_group;" ::: "memory")
#define CP_WAIT(n)  asm volatile("cp.async.wait_group %0;" :: "n"(n) : "memory")

// ---------------------------------------------------------------------------
// Split fp32 -> fp16 hi + fp16 lo
// ---------------------------------------------------------------------------
__global__ void split_f32h(const float* __restrict__ in, __half* __restrict__ hi,
                           __half* __restrict__ lo, int n4)
{
    int i = blockIdx.x * blockDim.x + threadIdx.x;
    if (i >= n4) return;
    float4 v = ((const float4*)in)[i];
    __half h0 = __float2half_rn(v.x);
    __half h1 = __float2half_rn(v.y);
    __half h2 = __float2half_rn(v.z);
    __half h3 = __float2half_rn(v.w);
    __half l0 = __float2half_rn(v.x - __half2float(h0));
    __half l1 = __float2half_rn(v.y - __half2float(h1));
    __half l2 = __float2half_rn(v.z - __half2float(h2));
    __half l3 = __float2half_rn(v.w - __half2float(h3));
    ((__half2*)hi)[2*i]   = __halves2half2(h0, h1);
    ((__half2*)hi)[2*i+1] = __halves2half2(h2, h3);
    ((__half2*)lo)[2*i]   = __halves2half2(l0, l1);
    ((__half2*)lo)[2*i+1] = __halves2half2(l2, l3);
}

// Convert 4 fp32 weight matrices to fp16 into one stacked buffer
__global__ void conv_w4(const float* __restrict__ a, const float* __restrict__ b,
                        const float* __restrict__ c, const float* __restrict__ d,
                        __half* __restrict__ out, int n4)
{
    int i = blockIdx.x * blockDim.x + threadIdx.x;
    if (i >= 4 * n4) return;
    int seg = i / n4;
    int j = i - seg * n4;
    const float* src = (seg == 0) ? a : (seg == 1) ? b : (seg == 2) ? c : d;
    float4 v = ((const float4*)src)[j];
    __half2 p0 = __floats2half2_rn(v.x, v.y);
    __half2 p1 = __floats2half2_rn(v.z, v.w);
    ((__half2*)out)[(size_t)seg * n4 * 2 + 2 * j]     = p0;
    ((__half2*)out)[(size_t)seg * n4 * 2 + 2 * j + 1] = p1;
}

// ---------------------------------------------------------------------------
// HMMA 2-term fp16-split GEMM: out[m][n] = sum_k X[m][k]*W[n][k]
//   = Xh*Wh + Xl*Wh  (dropped X*(W-Wh), rel-RMS ~1.4e-4)
// 128x128 block, 8 warps (64x32 warp tile), BK=32, cp.async double buffer.
// MODE 0: fused QKV (N range [0,3072)); fp16 scatter to [b][h][s][dh], Q scaled
// MODE 1: fp32 row-major + bias
// ---------------------------------------------------------------------------
#define TILE_B   10240          // 128 * 80
#define STAGE_B  30720          // 3 tiles (Xh, Xl, Wh)
#define GEMM_SMEM (2*STAGE_B)   // 61440

template<int MODE>
__global__ __launch_bounds__(256)
void gemm_mma(const __half* __restrict__ Xh, const __half* __restrict__ Xl,
              const __half* __restrict__ W, const float* __restrict__ bias,
              float* __restrict__ outF, __half* __restrict__ oQ,
              __half* __restrict__ oK, __half* __restrict__ oV)
{
    extern __shared__ __align__(128) char smem[];
    const int tid  = threadIdx.x;
    const int lane = tid & 31;
    const int wid  = tid >> 5;
    const int m0 = blockIdx.y * 128;
    const int n0 = blockIdx.x * 128;
    const int wm = (wid & 1) * 64;
    const int wn = (wid >> 1) * 32;
    const uint32_t sb = smem_u32(smem);

    const uint32_t aOff = (uint32_t)((lane & 15) * 80 + (lane >> 4) * 16);
    const uint32_t bOff = (uint32_t)(((lane & 7) + (lane >> 4) * 8) * 80 + ((lane >> 3) & 1) * 16);

    float acc[4][4][4];
#pragma unroll
    for (int i = 0; i < 4; i++)
#pragma unroll
        for (int j = 0; j < 4; j++)
#pragma unroll
            for (int q = 0; q < 4; q++) acc[i][j][q] = 0.f;

    auto issue_stage = [&](int c) {
        const uint32_t stage = sb + (uint32_t)(c & 1) * STAGE_B;
        const int kt = c * 32;
#pragma unroll
        for (int i = 0; i < 6; i++) {
            const int idx = i * 256 + tid;       // 0..1535
            const int tileI = idx >> 9;          // 0..2
            const int loc = idx & 511;
            const int row = loc >> 2;
            const int ch  = loc & 3;
            const __half* g;
            if (tileI == 0)      g = Xh + (size_t)(m0 + row) * D_ + kt + ch * 8;
            else if (tileI == 1) g = Xl + (size_t)(m0 + row) * D_ + kt + ch * 8;
            else                 g = W  + (size_t)(n0 + row) * D_ + kt + ch * 8;
            cp_async16(stage + (uint32_t)(tileI * TILE_B + row * 80 + ch * 16), g);
        }
        CP_COMMIT();
    };

    issue_stage(0);

    for (int c = 0; c < D_ / 32; ++c) {
        if (c + 1 < D_ / 32) { issue_stage(c + 1); CP_WAIT(1); }
        else                 { CP_WAIT(0); }
        __syncthreads();

        const uint32_t st  = sb + (uint32_t)(c & 1) * STAGE_B;
        const uint32_t aHi = st + 0 * TILE_B + (uint32_t)wm * 80 + aOff;
        const uint32_t aLo = st + 1 * TILE_B + (uint32_t)wm * 80 + aOff;
        const uint32_t bW  = st + 2 * TILE_B + (uint32_t)wn * 80 + bOff;

#pragma unroll
        for (int ks = 0; ks < 2; ks++) {
            const uint32_t ka = (uint32_t)ks * 32;
            uint32_t ah[4][4], bh[2][4];
#pragma unroll
            for (int mt = 0; mt < 4; mt++) ldsm4(aHi + (uint32_t)mt * (16 * 80) + ka, ah[mt]);
#pragma unroll
            for (int p = 0; p < 2; p++)    ldsm4(bW + (uint32_t)p * (16 * 80) + ka, bh[p]);
#pragma unroll
            for (int mt = 0; mt < 4; mt++)
#pragma unroll
                for (int nt = 0; nt < 4; nt++)
                    mma_f16(acc[mt][nt], ah[mt], &bh[nt >> 1][(nt & 1) * 2]);

            uint32_t al[4][4];
#pragma unroll
            for (int mt = 0; mt < 4; mt++) ldsm4(aLo + (uint32_t)mt * (16 * 80) + ka, al[mt]);
#pragma unroll
            for (int mt = 0; mt < 4; mt++)
#pragma unroll
                for (int nt = 0; nt < 4; nt++)
                    mma_f16(acc[mt][nt], al[mt], &bh[nt >> 1][(nt & 1) * 2]);
        }
        __syncthreads();
    }

    const int g = lane >> 2;
    const int t = lane & 3;
    if (MODE == 0) {
        const int proj = n0 >> 10;                 // 0=Q 1=K 2=V (n0 mult of 128)
        __half* dst = (proj == 0) ? oQ : (proj == 1) ? oK : oV;
        const float scl = (proj == 0) ? SCALE_ : 1.0f;
        const int cb = n0 & 1023;
#pragma unroll
        for (int mt = 0; mt < 4; mt++) {
            const int r0 = m0 + wm + mt * 16 + g;
            const int r1 = r0 + 8;
            const int b0i = r0 >> 11, s0 = r0 & 2047;
            const int b1i = r1 >> 11, s1 = r1 & 2047;
#pragma unroll
            for (int nt = 0; nt < 4; nt++) {
                const int cc = cb + wn + nt * 8 + t * 2;
                const int h = cc >> 6, d = cc & 63;
                __half2 v0 = __floats2half2_rn(acc[mt][nt][0] * scl, acc[mt][nt][1] * scl);
                __half2 v1 = __floats2half2_rn(acc[mt][nt][2] * scl, acc[mt][nt][3] * scl);
                *(__half2*)(dst + (((size_t)(b0i * H_ + h) * S_ + s0) * DH_ + d)) = v0;
                *(__half2*)(dst + (((size_t)(b1i * H_ + h) * S_ + s1) * DH_ + d)) = v1;
            }
        }
    } else {
#pragma unroll
        for (int mt = 0; mt < 4; mt++) {
            const int r0 = m0 + wm + mt * 16 + g;
            const int r1 = r0 + 8;
#pragma unroll
            for (int nt = 0; nt < 4; nt++) {
                const int col = n0 + wn + nt * 8 + t * 2;
                float2 bv = *(const float2*)(bias + col);
                float2 v0 = make_float2(acc[mt][nt][0] + bv.x, acc[mt][nt][1] + bv.y);
                float2 v1 = make_float2(acc[mt][nt][2] + bv.x, acc[mt][nt][3] + bv.y);
                *(float2*)(outF + (size_t)r0 * D_ + col) = v0;
                *(float2*)(outF + (size_t)r1 * D_ + col) = v1;
            }
        }
    }
}

// ---------------------------------------------------------------------------
// HMMA flash attention (fp16 QK^T and PV, fp32 softmax/accum)
// One CTA = one (b,h) x 128 queries. 8 warps x m16. 64-key blocks, double buf.
// Epilogue writes split-fp16 Ah/Al directly.
// ---------------------------------------------------------------------------
#define KSTR      144
#define Q_BYTES   (128*KSTR)           // 18432
#define KV_HALF   (64*KSTR)            // 9216
#define KV_STAGE  (2*KV_HALF)          // 18432
#define ATTN_SMEM (Q_BYTES + 2*KV_STAGE)  // 55296

__global__ __launch_bounds__(256)
void attn_mma(const __half* __restrict__ Q, const __half* __restrict__ K,
              const __half* __restrict__ V, __half* __restrict__ Ah,
              __half* __restrict__ Al)
{
    extern __shared__ __align__(128) char smem[];
    const uint32_t sb = smem_u32(smem);
    const int tid  = threadIdx.x;
    const int lane = tid & 31;
    const int wid  = tid >> 5;
    const int bh = blockIdx.y;
    const int q0 = blockIdx.x * 128;
    const __half* Qp = Q + (size_t)bh * S_ * DH_;
    const __half* Kp = K + (size_t)bh * S_ * DH_;
    const __half* Vp = V + (size_t)bh * S_ * DH_;

    const uint32_t bOff = (uint32_t)(((lane & 7) + (lane >> 4) * 8) * KSTR + ((lane >> 3) & 1) * 16);
    const uint32_t vOff = (uint32_t)((lane & 15) * KSTR + (lane >> 4) * 16);

#pragma unroll
    for (int i = 0; i < 4; i++) {
        int idx = tid + i * 256;
        int row = idx >> 3, ch = idx & 7;
        cp_async16(sb + (uint32_t)(row * KSTR + ch * 16),
                   Qp + (size_t)(q0 + row) * DH_ + ch * 8);
    }
    CP_COMMIT();

    auto issue_kv = [&](int c) {
        const uint32_t st = sb + Q_BYTES + (uint32_t)(c & 1) * KV_STAGE;
        const int kt = c * 64;
#pragma unroll
        for (int i = 0; i < 4; i++) {
            int idx = tid + i * 256;
            int loc = idx & 511;
            int row = loc >> 3, ch = loc & 7;
            const __half* src = (idx < 512) ? (Kp + (size_t)(kt + row) * DH_ + ch * 8)
                                            : (Vp + (size_t)(kt + row) * DH_ + ch * 8);
            uint32_t dst = st + (uint32_t)((idx < 512 ? 0 : KV_HALF) + row * KSTR + ch * 16);
            cp_async16(dst, src);
        }
        CP_COMMIT();
    };

    issue_kv(0);
    CP_WAIT(1);
    __syncthreads();

    uint32_t qf[4][4];
    const uint32_t qAddr = sb + (uint32_t)((wid * 16 + (lane & 15)) * KSTR + (lane >> 4) * 16);
#pragma unroll
    for (int kf = 0; kf < 4; kf++) ldsm4(qAddr + (uint32_t)kf * 32, qf[kf]);

    float of[8][4];
#pragma unroll
    for (int t = 0; t < 8; t++)
#pragma unroll
        for (int q = 0; q < 4; q++) of[t][q] = 0.f;
    float m_lo = -1e30f, m_hi = -1e30f, l_lo = 0.f, l_hi = 0.f;

    for (int c = 0; c < S_ / 64; ++c) {
        if (c + 1 < S_ / 64) { issue_kv(c + 1); CP_WAIT(1); }
        else                 { CP_WAIT(0); }
        __syncthreads();

        const uint32_t Kst = sb + Q_BYTES + (uint32_t)(c & 1) * KV_STAGE;
        const uint32_t Vst = Kst + KV_HALF;

        float sf[8][4];
#pragma unroll
        for (int t = 0; t < 8; t++)
#pragma unroll
            for (int q = 0; q < 4; q++) sf[t][q] = 0.f;
#pragma unroll
        for (int kf = 0; kf < 4; kf++) {
            uint32_t kb[4][4];
#pragma unroll
            for (int kg = 0; kg < 4; kg++)
                ldsm4(Kst + (uint32_t)(kg * 16 * KSTR) + (uint32_t)kf * 32 + bOff, kb[kg]);
#pragma unroll
            for (int kg = 0; kg < 4; kg++) {
                mma_f16(sf[2 * kg],     qf[kf], &kb[kg][0]);
                mma_f16(sf[2 * kg + 1], qf[kf], &kb[kg][2]);
            }
        }

        float mt_lo = -1e30f, mt_hi = -1e30f;
#pragma unroll
        for (int t = 0; t < 8; t++) {
            mt_lo = fmaxf(mt_lo, fmaxf(sf[t][0], sf[t][1]));
            mt_hi = fmaxf(mt_hi, fmaxf(sf[t][2], sf[t][3]));
        }
        mt_lo = fmaxf(mt_lo, __shfl_xor_sync(0xffffffffu, mt_lo, 1));
        mt_lo = fmaxf(mt_lo, __shfl_xor_sync(0xffffffffu, mt_lo, 2));
        mt_hi = fmaxf(mt_hi, __shfl_xor_sync(0xffffffffu, mt_hi, 1));
        mt_hi = fmaxf(mt_hi, __shfl_xor_sync(0xffffffffu, mt_hi, 2));
        const float mn_lo = fmaxf(m_lo, mt_lo);
        const float mn_hi = fmaxf(m_hi, mt_hi);
        const float corr_lo = __expf(m_lo - mn_lo);
        const float corr_hi = __expf(m_hi - mn_hi);
        m_lo = mn_lo; m_hi = mn_hi;

        float ls_lo = 0.f, ls_hi = 0.f;
#pragma unroll
        for (int t = 0; t < 8; t++) {
            sf[t][0] = __expf(sf[t][0] - mn_lo);
            sf[t][1] = __expf(sf[t][1] - mn_lo);
            sf[t][2] = __expf(sf[t][2] - mn_hi);
            sf[t][3] = __expf(sf[t][3] - mn_hi);
            ls_lo += sf[t][0] + sf[t][1];
            ls_hi += sf[t][2] + sf[t][3];
        }
        l_lo = l_lo * corr_lo + ls_lo;
        l_hi = l_hi * corr_hi + ls_hi;
#pragma unroll
        for (int t = 0; t < 8; t++) {
            of[t][0] *= corr_lo; of[t][1] *= corr_lo;
            of[t][2] *= corr_hi; of[t][3] *= corr_hi;
        }

        uint32_t pa[4][4];
#pragma unroll
        for (int kf = 0; kf < 4; kf++) {
            pa[kf][0] = h2_u32(__floats2half2_rn(sf[2 * kf][0],     sf[2 * kf][1]));
            pa[kf][1] = h2_u32(__floats2half2_rn(sf[2 * kf][2],     sf[2 * kf][3]));
            pa[kf][2] = h2_u32(__floats2half2_rn(sf[2 * kf + 1][0], sf[2 * kf + 1][1]));
            pa[kf][3] = h2_u32(__floats2half2_rn(sf[2 * kf + 1][2], sf[2 * kf + 1][3]));
        }

#pragma unroll
        for (int kf = 0; kf < 4; kf++) {
            uint32_t vb[4][4];
#pragma unroll
            for (int ng = 0; ng < 4; ng++)
                ldsm4t(Vst + (uint32_t)(kf * 16 * KSTR) + (uint32_t)(ng * 32) + vOff, vb[ng]);
#pragma unroll
            for (int ng = 0; ng < 4; ng++) {
                mma_f16(of[2 * ng],     pa[kf], &vb[ng][0]);
                mma_f16(of[2 * ng + 1], pa[kf], &vb[ng][2]);
            }
        }
        __syncthreads();
    }

    l_lo += __shfl_xor_sync(0xffffffffu, l_lo, 1);
    l_lo += __shfl_xor_sync(0xffffffffu, l_lo, 2);
    l_hi += __shfl_xor_sync(0xffffffffu, l_hi, 1);
    l_hi += __shfl_xor_sync(0xffffffffu, l_hi, 2);
    const float inv_lo = 1.f / l_lo;
    const float inv_hi = 1.f / l_hi;

    const int b = bh >> 4;
    const int h = bh & 15;
    const int row0 = q0 + wid * 16 + (lane >> 2);
    const int row1 = row0 + 8;
#pragma unroll
    for (int t = 0; t < 8; t++) {
        const int colG = h * DH_ + t * 8 + (lane & 3) * 2;
        float v0 = of[t][0] * inv_lo, v1 = of[t][1] * inv_lo;
        float v2 = of[t][2] * inv_hi, v3 = of[t][3] * inv_hi;
        __half h0 = __float2half_rn(v0), h1 = __float2half_rn(v1);
        __half h2 = __float2half_rn(v2), h3 = __float2half_rn(v3);
        __half e0 = __float2half_rn(v0 - __half2float(h0));
        __half e1 = __float2half_rn(v1 - __half2float(h1));
        __half e2 = __float2half_rn(v2 - __half2float(h2));
        __half e3 = __float2half_rn(v3 - __half2float(h3));
        size_t a0 = (size_t)(b * S_ + row0) * D_ + colG;
        size_t a1 = (size_t)(b * S_ + row1) * D_ + colG;
        *(__half2*)(Ah + a0) = __halves2half2(h0, h1);
        *(__half2*)(Al + a0) = __halves2half2(e0, e1);
        *(__half2*)(Ah + a1) = __halves2half2(h2, h3);
        *(__half2*)(Al + a1) = __halves2half2(e2, e3);
    }
}

// ---------------------------------------------------------------------------
extern "C" void kernel_launch(void* const* d_in, const int* in_sizes, int n_in,
                              void* d_out, int out_size)
{
    const float* x  = (const float*)d_in[0];
    const float* Wq = (const float*)d_in[1];
    const float* Wk = (const float*)d_in[2];
    const float* Wv = (const float*)d_in[3];
    const float* Wo = (const float*)d_in[4];
    const float* bo = (const float*)d_in[5];
    float* out = (float*)d_out;

    __half *Qh, *Kh, *Vh, *Xh, *Xl, *Wf, *Ah, *Al;
    cudaGetSymbolAddress((void**)&Qh, g_Qh);
    cudaGetSymbolAddress((void**)&Kh, g_Kh);
    cudaGetSymbolAddress((void**)&Vh, g_Vh);
    cudaGetSymbolAddress((void**)&Xh, g_Xh);
    cudaGetSymbolAddress((void**)&Xl, g_Xl);
    cudaGetSymbolAddress((void**)&Wf, g_Wf);
    cudaGetSymbolAddress((void**)&Ah, g_Ah);
    cudaGetSymbolAddress((void**)&Al, g_Al);

    static bool attr_set = false;
    if (!attr_set) {
        cudaFuncSetAttribute(gemm_mma<0>, cudaFuncAttributeMaxDynamicSharedMemorySize, GEMM_SMEM);
        cudaFuncSetAttribute(gemm_mma<1>, cudaFuncAttributeMaxDynamicSharedMemorySize, GEMM_SMEM);
        cudaFuncSetAttribute(attn_mma,    cudaFuncAttributeMaxDynamicSharedMemorySize, ATTN_SMEM);
        attr_set = true;
    }

    const int nX4 = M_ * D_ / 4;       // 1048576
    const int nW4 = D_ * D_ / 4;       // 262144
    split_f32h<<<(nX4 + 255) / 256, 256>>>(x, Xh, Xl, nX4);
    conv_w4<<<(4 * nW4 + 255) / 256, 256>>>(Wq, Wk, Wv, Wo, Wf, nW4);

    // Fused QKV projection (N = 3072)
    gemm_mma<0><<<dim3(3 * D_ / 128, M_ / 128), 256, GEMM_SMEM>>>(
        Xh, Xl, Wf, nullptr, nullptr, Qh, Kh, Vh);

    attn_mma<<<dim3(S_ / 128, B_ * H_), 256, ATTN_SMEM>>>(Qh, Kh, Vh, Ah, Al);

    // Output projection
    gemm_mma<1><<<dim3(D_ / 128, M_ / 128), 256, GEMM_SMEM>>>(
        Ah, Al, Wf + 3 * (size_t)D_ * D_, bo, out, nullptr, nullptr, nullptr);
}

// round 8
// speedup vs baseline: 7.8698x; 1.4388x over previous
#include <cuda_runtime.h>
#include <cuda_fp16.h>
#include <stdint.h>
#include <math.h>

// Problem constants
#define B_  2
#define S_  2048
#define D_  1024
#define H_  16
#define DH_ 64
#define M_  (B_*S_)          // 4096
#define SCALE_ 0.125f

// ---------------------------------------------------------------------------
// Scratch (__device__ globals; allocation-free rule)
// ---------------------------------------------------------------------------
static __device__ __half g_Qh[B_*H_*S_*DH_];   // [b][h][s][dh] fp16 (pre-scaled)
static __device__ __half g_Kh[B_*H_*S_*DH_];
static __device__ __half g_Vh[B_*H_*S_*DH_];
static __device__ __half g_Xh[M_*D_];          // fp16 hidden_states
static __device__ __half g_Wf[4*D_*D_];        // fp16 W: [Wq;Wk;Wv;Wo] stacked
static __device__ __half g_Ah[M_*D_];          // fp16 attention out [b][s][d]

// ---------------------------------------------------------------------------
// Base-ISA tensor-core helpers
// ---------------------------------------------------------------------------
__device__ __forceinline__ uint32_t smem_u32(const void* p) {
    uint32_t a;
    asm("{ .reg .u64 t; cvta.to.shared.u64 t, %1; cvt.u32.u64 %0, t; }" : "=r"(a) : "l"(p));
    return a;
}
__device__ __forceinline__ uint32_t h2_u32(__half2 h) {
    union { __half2 h; uint32_t u; } cvt;
    cvt.h = h;
    return cvt.u;
}
__device__ __forceinline__ void ldsm4(uint32_t addr, uint32_t* r) {
    asm volatile("ldmatrix.sync.aligned.m8n8.x4.shared.b16 {%0,%1,%2,%3}, [%4];"
                 : "=r"(r[0]), "=r"(r[1]), "=r"(r[2]), "=r"(r[3]) : "r"(addr));
}
__device__ __forceinline__ void ldsm4t(uint32_t addr, uint32_t* r) {
    asm volatile("ldmatrix.sync.aligned.m8n8.x4.trans.shared.b16 {%0,%1,%2,%3}, [%4];"
                 : "=r"(r[0]), "=r"(r[1]), "=r"(r[2]), "=r"(r[3]) : "r"(addr));
}
__device__ __forceinline__ void mma_f16(float* d, const uint32_t* a, const uint32_t* b) {
    asm volatile("mma.sync.aligned.m16n8k16.row.col.f32.f16.f16.f32 "
                 "{%0,%1,%2,%3},{%4,%5,%6,%7},{%8,%9},{%0,%1,%2,%3};"
                 : "+f"(d[0]), "+f"(d[1]), "+f"(d[2]), "+f"(d[3])
                 : "r"(a[0]), "r"(a[1]), "r"(a[2]), "r"(a[3]), "r"(b[0]), "r"(b[1]));
}
__device__ __forceinline__ void cp_async16(uint32_t dst, const void* src) {
    asm volatile("cp.async.cg.shared.global [%0], [%1], 16;" :: "r"(dst), "l"(src));
}
#define CP_COMMIT() asm volatile("cp.async.commit_group;" ::: "memory")
#define CP_WAIT(n)  asm volatile("cp.async.wait_group %0;" :: "n"(n) : "memory")

// ---------------------------------------------------------------------------
// fp32 -> fp16 converts
// ---------------------------------------------------------------------------
__global__ void conv_h(const float* __restrict__ in, __half* __restrict__ out, int n4)
{
    int i = blockIdx.x * blockDim.x + threadIdx.x;
    if (i >= n4) return;
    float4 v = ((const float4*)in)[i];
    ((__half2*)out)[2*i]   = __floats2half2_rn(v.x, v.y);
    ((__half2*)out)[2*i+1] = __floats2half2_rn(v.z, v.w);
}

__global__ void conv_w4(const float* __restrict__ a, const float* __restrict__ b,
                        const float* __restrict__ c, const float* __restrict__ d,
                        __half* __restrict__ out, int n4)
{
    int i = blockIdx.x * blockDim.x + threadIdx.x;
    if (i >= 4 * n4) return;
    int seg = i / n4;
    int j = i - seg * n4;
    const float* src = (seg == 0) ? a : (seg == 1) ? b : (seg == 2) ? c : d;
    float4 v = ((const float4*)src)[j];
    ((__half2*)out)[(size_t)seg * n4 * 2 + 2 * j]     = __floats2half2_rn(v.x, v.y);
    ((__half2*)out)[(size_t)seg * n4 * 2 + 2 * j + 1] = __floats2half2_rn(v.z, v.w);
}

// ---------------------------------------------------------------------------
// Pure-fp16 HMMA GEMM: out[m][n] = sum_k X[m][k]*W[n][k]
// 128x128 block, 8 warps (64x32 warp tile), BK=32, 3-stage cp.async pipeline.
// MODE 0: fused QKV (N in [0,3072)); fp16 scatter to [b][h][s][dh], Q scaled
// MODE 1: fp32 row-major + bias
// ---------------------------------------------------------------------------
#define TILE_B   10240          // 128 rows * 80 B
#define STAGE_B  20480          // 2 tiles (X, W)
#define GEMM_SMEM (3*STAGE_B)   // 61440
#define NCHUNK   (D_/32)        // 32

template<int MODE>
__global__ __launch_bounds__(256)
void gemm_mma(const __half* __restrict__ X, const __half* __restrict__ W,
              const float* __restrict__ bias, float* __restrict__ outF,
              __half* __restrict__ oQ, __half* __restrict__ oK, __half* __restrict__ oV)
{
    extern __shared__ __align__(128) char smem[];
    const int tid  = threadIdx.x;
    const int lane = tid & 31;
    const int wid  = tid >> 5;
    const int m0 = blockIdx.y * 128;
    const int n0 = blockIdx.x * 128;
    const int wm = (wid & 1) * 64;
    const int wn = (wid >> 1) * 32;
    const uint32_t sb = smem_u32(smem);

    const uint32_t aOff = (uint32_t)((lane & 15) * 80 + (lane >> 4) * 16);
    const uint32_t bOff = (uint32_t)(((lane & 7) + (lane >> 4) * 8) * 80 + ((lane >> 3) & 1) * 16);

    float acc[4][4][4];
#pragma unroll
    for (int i = 0; i < 4; i++)
#pragma unroll
        for (int j = 0; j < 4; j++)
#pragma unroll
            for (int q = 0; q < 4; q++) acc[i][j][q] = 0.f;

    auto issue_stage = [&](int c) {
        const uint32_t stage = sb + (uint32_t)(c % 3) * STAGE_B;
        const int kt = c * 32;
#pragma unroll
        for (int i = 0; i < 4; i++) {
            const int idx = i * 256 + tid;       // 0..1023
            const int tileI = idx >> 9;          // 0..1
            const int loc = idx & 511;
            const int row = loc >> 2;
            const int ch  = loc & 3;
            const __half* g = (tileI == 0) ? (X + (size_t)(m0 + row) * D_ + kt + ch * 8)
                                           : (W + (size_t)(n0 + row) * D_ + kt + ch * 8);
            cp_async16(stage + (uint32_t)(tileI * TILE_B + row * 80 + ch * 16), g);
        }
        CP_COMMIT();
    };

    issue_stage(0);
    issue_stage(1);

    for (int c = 0; c < NCHUNK; ++c) {
        CP_WAIT(1);            // stage c landed
        __syncthreads();       // all warps past stage c-1 reads; buffer (c+2)%3 free
        if (c + 2 < NCHUNK) issue_stage(c + 2);

        const uint32_t st = sb + (uint32_t)(c % 3) * STAGE_B;
        const uint32_t aT = st + (uint32_t)wm * 80 + aOff;
        const uint32_t bT = st + TILE_B + (uint32_t)wn * 80 + bOff;

#pragma unroll
        for (int ks = 0; ks < 2; ks++) {
            const uint32_t ka = (uint32_t)ks * 32;
            uint32_t ah[4][4], bh[2][4];
#pragma unroll
            for (int mt = 0; mt < 4; mt++) ldsm4(aT + (uint32_t)mt * (16 * 80) + ka, ah[mt]);
#pragma unroll
            for (int p = 0; p < 2; p++)    ldsm4(bT + (uint32_t)p * (16 * 80) + ka, bh[p]);
#pragma unroll
            for (int mt = 0; mt < 4; mt++)
#pragma unroll
                for (int nt = 0; nt < 4; nt++)
                    mma_f16(acc[mt][nt], ah[mt], &bh[nt >> 1][(nt & 1) * 2]);
        }
    }

    const int g = lane >> 2;
    const int t = lane & 3;
    if (MODE == 0) {
        const int proj = n0 >> 10;                 // 0=Q 1=K 2=V
        __half* dst = (proj == 0) ? oQ : (proj == 1) ? oK : oV;
        const float scl = (proj == 0) ? SCALE_ : 1.0f;
        const int cb = n0 & 1023;
#pragma unroll
        for (int mt = 0; mt < 4; mt++) {
            const int r0 = m0 + wm + mt * 16 + g;
            const int r1 = r0 + 8;
            const int b0i = r0 >> 11, s0 = r0 & 2047;
            const int b1i = r1 >> 11, s1 = r1 & 2047;
#pragma unroll
            for (int nt = 0; nt < 4; nt++) {
                const int cc = cb + wn + nt * 8 + t * 2;
                const int h = cc >> 6, d = cc & 63;
                __half2 v0 = __floats2half2_rn(acc[mt][nt][0] * scl, acc[mt][nt][1] * scl);
                __half2 v1 = __floats2half2_rn(acc[mt][nt][2] * scl, acc[mt][nt][3] * scl);
                *(__half2*)(dst + (((size_t)(b0i * H_ + h) * S_ + s0) * DH_ + d)) = v0;
                *(__half2*)(dst + (((size_t)(b1i * H_ + h) * S_ + s1) * DH_ + d)) = v1;
            }
        }
    } else {
#pragma unroll
        for (int mt = 0; mt < 4; mt++) {
            const int r0 = m0 + wm + mt * 16 + g;
            const int r1 = r0 + 8;
#pragma unroll
            for (int nt = 0; nt < 4; nt++) {
                const int col = n0 + wn + nt * 8 + t * 2;
                float2 bv = *(const float2*)(bias + col);
                float2 v0 = make_float2(acc[mt][nt][0] + bv.x, acc[mt][nt][1] + bv.y);
                float2 v1 = make_float2(acc[mt][nt][2] + bv.x, acc[mt][nt][3] + bv.y);
                *(float2*)(outF + (size_t)r0 * D_ + col) = v0;
                *(float2*)(outF + (size_t)r1 * D_ + col) = v1;
            }
        }
    }
}

// ---------------------------------------------------------------------------
// HMMA flash attention (fp16 QK^T and PV, fp32 softmax/accum)
// One CTA = one (b,h) x 128 queries. 8 warps x m16. 64-key blocks,
// 3-stage KV pipeline, one barrier per block-iter.
// Epilogue writes fp16 Ah directly ([b][s][d]).
// ---------------------------------------------------------------------------
#define KSTR      144
#define Q_BYTES   (128*KSTR)           // 18432
#define KV_HALF   (64*KSTR)            // 9216
#define KV_STAGE  (2*KV_HALF)          // 18432
#define ATTN_SMEM (Q_BYTES + 3*KV_STAGE)  // 73728
#define NIT       (S_/64)              // 32

__global__ __launch_bounds__(256)
void attn_mma(const __half* __restrict__ Q, const __half* __restrict__ K,
              const __half* __restrict__ V, __half* __restrict__ Ah)
{
    extern __shared__ __align__(128) char smem[];
    const uint32_t sb = smem_u32(smem);
    const int tid  = threadIdx.x;
    const int lane = tid & 31;
    const int wid  = tid >> 5;
    const int bh = blockIdx.y;
    const int q0 = blockIdx.x * 128;
    const __half* Qp = Q + (size_t)bh * S_ * DH_;
    const __half* Kp = K + (size_t)bh * S_ * DH_;
    const __half* Vp = V + (size_t)bh * S_ * DH_;

    const uint32_t bOff = (uint32_t)(((lane & 7) + (lane >> 4) * 8) * KSTR + ((lane >> 3) & 1) * 16);
    const uint32_t vOff = (uint32_t)((lane & 15) * KSTR + (lane >> 4) * 16);

    auto issue_kv = [&](int c) {
        const uint32_t st = sb + Q_BYTES + (uint32_t)(c % 3) * KV_STAGE;
        const int kt = c * 64;
#pragma unroll
        for (int i = 0; i < 4; i++) {
            int idx = tid + i * 256;
            int loc = idx & 511;
            int row = loc >> 3, ch = loc & 7;
            const __half* src = (idx < 512) ? (Kp + (size_t)(kt + row) * DH_ + ch * 8)
                                            : (Vp + (size_t)(kt + row) * DH_ + ch * 8);
            uint32_t dst = st + (uint32_t)((idx < 512 ? 0 : KV_HALF) + row * KSTR + ch * 16);
            cp_async16(dst, src);
        }
        CP_COMMIT();
    };

    // prologue: group0 = Q + KV0, group1 = KV1
    {
#pragma unroll
        for (int i = 0; i < 4; i++) {
            int idx = tid + i * 256;
            int row = idx >> 3, ch = idx & 7;
            cp_async16(sb + (uint32_t)(row * KSTR + ch * 16),
                       Qp + (size_t)(q0 + row) * DH_ + ch * 8);
        }
        // fold KV0 into the same commit group as Q
        const uint32_t st = sb + Q_BYTES;
#pragma unroll
        for (int i = 0; i < 4; i++) {
            int idx = tid + i * 256;
            int loc = idx & 511;
            int row = loc >> 3, ch = loc & 7;
            const __half* src = (idx < 512) ? (Kp + (size_t)row * DH_ + ch * 8)
                                            : (Vp + (size_t)row * DH_ + ch * 8);
            uint32_t dst = st + (uint32_t)((idx < 512 ? 0 : KV_HALF) + row * KSTR + ch * 16);
            cp_async16(dst, src);
        }
        CP_COMMIT();
    }
    issue_kv(1);

    uint32_t qf[4][4];
    float of[8][4];
#pragma unroll
    for (int t = 0; t < 8; t++)
#pragma unroll
        for (int q = 0; q < 4; q++) of[t][q] = 0.f;
    float m_lo = -1e30f, m_hi = -1e30f, l_lo = 0.f, l_hi = 0.f;

    for (int c = 0; c < NIT; ++c) {
        CP_WAIT(1);
        __syncthreads();
        if (c == 0) {
            const uint32_t qAddr = sb + (uint32_t)((wid * 16 + (lane & 15)) * KSTR + (lane >> 4) * 16);
#pragma unroll
            for (int kf = 0; kf < 4; kf++) ldsm4(qAddr + (uint32_t)kf * 32, qf[kf]);
        }
        if (c + 2 < NIT) issue_kv(c + 2);

        const uint32_t Kst = sb + Q_BYTES + (uint32_t)(c % 3) * KV_STAGE;
        const uint32_t Vst = Kst + KV_HALF;

        float sf[8][4];
#pragma unroll
        for (int t = 0; t < 8; t++)
#pragma unroll
            for (int q = 0; q < 4; q++) sf[t][q] = 0.f;
#pragma unroll
        for (int kf = 0; kf < 4; kf++) {
            uint32_t kb[4][4];
#pragma unroll
            for (int kg = 0; kg < 4; kg++)
                ldsm4(Kst + (uint32_t)(kg * 16 * KSTR) + (uint32_t)kf * 32 + bOff, kb[kg]);
#pragma unroll
            for (int kg = 0; kg < 4; kg++) {
                mma_f16(sf[2 * kg],     qf[kf], &kb[kg][0]);
                mma_f16(sf[2 * kg + 1], qf[kf], &kb[kg][2]);
            }
        }

        float mt_lo = -1e30f, mt_hi = -1e30f;
#pragma unroll
        for (int t = 0; t < 8; t++) {
            mt_lo = fmaxf(mt_lo, fmaxf(sf[t][0], sf[t][1]));
            mt_hi = fmaxf(mt_hi, fmaxf(sf[t][2], sf[t][3]));
        }
        mt_lo = fmaxf(mt_lo, __shfl_xor_sync(0xffffffffu, mt_lo, 1));
        mt_lo = fmaxf(mt_lo, __shfl_xor_sync(0xffffffffu, mt_lo, 2));
        mt_hi = fmaxf(mt_hi, __shfl_xor_sync(0xffffffffu, mt_hi, 1));
        mt_hi = fmaxf(mt_hi, __shfl_xor_sync(0xffffffffu, mt_hi, 2));
        const float mn_lo = fmaxf(m_lo, mt_lo);
        const float mn_hi = fmaxf(m_hi, mt_hi);
        const float corr_lo = __expf(m_lo - mn_lo);
        const float corr_hi = __expf(m_hi - mn_hi);
        m_lo = mn_lo; m_hi = mn_hi;

        float ls_lo = 0.f, ls_hi = 0.f;
#pragma unroll
        for (int t = 0; t < 8; t++) {
            sf[t][0] = __expf(sf[t][0] - mn_lo);
            sf[t][1] = __expf(sf[t][1] - mn_lo);
            sf[t][2] = __expf(sf[t][2] - mn_hi);
            sf[t][3] = __expf(sf[t][3] - mn_hi);
            ls_lo += sf[t][0] + sf[t][1];
            ls_hi += sf[t][2] + sf[t][3];
        }
        l_lo = l_lo * corr_lo + ls_lo;
        l_hi = l_hi * corr_hi + ls_hi;
#pragma unroll
        for (int t = 0; t < 8; t++) {
            of[t][0] *= corr_lo; of[t][1] *= corr_lo;
            of[t][2] *= corr_hi; of[t][3] *= corr_hi;
        }

        uint32_t pa[4][4];
#pragma unroll
        for (int kf = 0; kf < 4; kf++) {
            pa[kf][0] = h2_u32(__floats2half2_rn(sf[2 * kf][0],     sf[2 * kf][1]));
            pa[kf][1] = h2_u32(__floats2half2_rn(sf[2 * kf][2],     sf[2 * kf][3]));
            pa[kf][2] = h2_u32(__floats2half2_rn(sf[2 * kf + 1][0], sf[2 * kf + 1][1]));
            pa[kf][3] = h2_u32(__floats2half2_rn(sf[2 * kf + 1][2], sf[2 * kf + 1][3]));
        }

#pragma unroll
        for (int kf = 0; kf < 4; kf++) {
            uint32_t vb[4][4];
#pragma unroll
            for (int ng = 0; ng < 4; ng++)
                ldsm4t(Vst + (uint32_t)(kf * 16 * KSTR) + (uint32_t)(ng * 32) + vOff, vb[ng]);
#pragma unroll
            for (int ng = 0; ng < 4; ng++) {
                mma_f16(of[2 * ng],     pa[kf], &vb[ng][0]);
                mma_f16(of[2 * ng + 1], pa[kf], &vb[ng][2]);
            }
        }
    }

    l_lo += __shfl_xor_sync(0xffffffffu, l_lo, 1);
    l_lo += __shfl_xor_sync(0xffffffffu, l_lo, 2);
    l_hi += __shfl_xor_sync(0xffffffffu, l_hi, 1);
    l_hi += __shfl_xor_sync(0xffffffffu, l_hi, 2);
    const float inv_lo = 1.f / l_lo;
    const float inv_hi = 1.f / l_hi;

    const int b = bh >> 4;
    const int h = bh & 15;
    const int row0 = q0 + wid * 16 + (lane >> 2);
    const int row1 = row0 + 8;
#pragma unroll
    for (int t = 0; t < 8; t++) {
        const int colG = h * DH_ + t * 8 + (lane & 3) * 2;
        size_t a0 = (size_t)(b * S_ + row0) * D_ + colG;
        size_t a1 = (size_t)(b * S_ + row1) * D_ + colG;
        *(__half2*)(Ah + a0) = __floats2half2_rn(of[t][0] * inv_lo, of[t][1] * inv_lo);
        *(__half2*)(Ah + a1) = __floats2half2_rn(of[t][2] * inv_hi, of[t][3] * inv_hi);
    }
}

// ---------------------------------------------------------------------------
extern "C" void kernel_launch(void* const* d_in, const int* in_sizes, int n_in,
                              void* d_out, int out_size)
{
    const float* x  = (const float*)d_in[0];
    const float* Wq = (const float*)d_in[1];
    const float* Wk = (const float*)d_in[2];
    const float* Wv = (const float*)d_in[3];
    const float* Wo = (const float*)d_in[4];
    const float* bo = (const float*)d_in[5];
    float* out = (float*)d_out;

    __half *Qh, *Kh, *Vh, *Xh, *Wf, *Ah;
    cudaGetSymbolAddress((void**)&Qh, g_Qh);
    cudaGetSymbolAddress((void**)&Kh, g_Kh);
    cudaGetSymbolAddress((void**)&Vh, g_Vh);
    cudaGetSymbolAddress((void**)&Xh, g_Xh);
    cudaGetSymbolAddress((void**)&Wf, g_Wf);
    cudaGetSymbolAddress((void**)&Ah, g_Ah);

    static bool attr_set = false;
    if (!attr_set) {
        cudaFuncSetAttribute(gemm_mma<0>, cudaFuncAttributeMaxDynamicSharedMemorySize, GEMM_SMEM);
        cudaFuncSetAttribute(gemm_mma<1>, cudaFuncAttributeMaxDynamicSharedMemorySize, GEMM_SMEM);
        cudaFuncSetAttribute(attn_mma,    cudaFuncAttributeMaxDynamicSharedMemorySize, ATTN_SMEM);
        attr_set = true;
    }

    const int nX4 = M_ * D_ / 4;       // 1048576
    const int nW4 = D_ * D_ / 4;       // 262144
    conv_h<<<(nX4 + 255) / 256, 256>>>(x, Xh, nX4);
    conv_w4<<<(4 * nW4 + 255) / 256, 256>>>(Wq, Wk, Wv, Wo, Wf, nW4);

    // Fused QKV projection (N = 3072)
    gemm_mma<0><<<dim3(3 * D_ / 128, M_ / 128), 256, GEMM_SMEM>>>(
        Xh, Wf, nullptr, nullptr, Qh, Kh, Vh);

    attn_mma<<<dim3(S_ / 128, B_ * H_), 256, ATTN_SMEM>>>(Qh, Kh, Vh, Ah);

    // Output projection
    gemm_mma<1><<<dim3(D_ / 128, M_ / 128), 256, GEMM_SMEM>>>(
        Ah, Wf + 3 * (size_t)D_ * D_, bo, out, nullptr, nullptr, nullptr);
}

// round 9
// speedup vs baseline: 8.1331x; 1.0335x over previous
#include <cuda_runtime.h>
#include <cuda_fp16.h>
#include <stdint.h>
#include <math.h>

// Problem constants
#define B_  2
#define S_  2048
#define D_  1024
#define H_  16
#define DH_ 64
#define M_  (B_*S_)          // 4096
#define SCALE_ 0.125f
#define QSCL_ 0.18033688f    // 0.125 * log2(e)

// ---------------------------------------------------------------------------
// Scratch (__device__ globals; allocation-free rule)
// ---------------------------------------------------------------------------
static __device__ __half g_Qh[B_*H_*S_*DH_];   // [b][h][s][dh] fp16, scaled by QSCL_
static __device__ __half g_Kh[B_*H_*S_*DH_];
static __device__ __half g_Vh[B_*H_*S_*DH_];
static __device__ __half g_Xh[M_*D_];
static __device__ __half g_Wf[4*D_*D_];
static __device__ __half g_Ah[M_*D_];

// ---------------------------------------------------------------------------
// Helpers
// ---------------------------------------------------------------------------
__device__ __forceinline__ uint32_t smem_u32(const void* p) {
    uint32_t a;
    asm("{ .reg .u64 t; cvta.to.shared.u64 t, %1; cvt.u32.u64 %0, t; }" : "=r"(a) : "l"(p));
    return a;
}
__device__ __forceinline__ uint32_t h2_u32(__half2 h) {
    union { __half2 h; uint32_t u; } cvt;
    cvt.h = h;
    return cvt.u;
}
__device__ __forceinline__ float ex2f(float x) {
    float y;
    asm("ex2.approx.ftz.f32 %0, %1;" : "=f"(y) : "f"(x));
    return y;
}
__device__ __forceinline__ void ldsm4(uint32_t addr, uint32_t* r) {
    asm volatile("ldmatrix.sync.aligned.m8n8.x4.shared.b16 {%0,%1,%2,%3}, [%4];"
                 : "=r"(r[0]), "=r"(r[1]), "=r"(r[2]), "=r"(r[3]) : "r"(addr));
}
__device__ __forceinline__ void ldsm4t(uint32_t addr, uint32_t* r) {
    asm volatile("ldmatrix.sync.aligned.m8n8.x4.trans.shared.b16 {%0,%1,%2,%3}, [%4];"
                 : "=r"(r[0]), "=r"(r[1]), "=r"(r[2]), "=r"(r[3]) : "r"(addr));
}
__device__ __forceinline__ void mma_f16(float* d, const uint32_t* a, const uint32_t* b) {
    asm volatile("mma.sync.aligned.m16n8k16.row.col.f32.f16.f16.f32 "
                 "{%0,%1,%2,%3},{%4,%5,%6,%7},{%8,%9},{%0,%1,%2,%3};"
                 : "+f"(d[0]), "+f"(d[1]), "+f"(d[2]), "+f"(d[3])
                 : "r"(a[0]), "r"(a[1]), "r"(a[2]), "r"(a[3]), "r"(b[0]), "r"(b[1]));
}
__device__ __forceinline__ void cp_async16(uint32_t dst, const void* src) {
    asm volatile("cp.async.cg.shared.global [%0], [%1], 16;" :: "r"(dst), "l"(src));
}
#define CP_COMMIT() asm volatile("cp.async.commit_group;" ::: "memory")
#define CP_WAIT(n)  asm volatile("cp.async.wait_group %0;" :: "n"(n) : "memory")

// ---------------------------------------------------------------------------
// fp32 -> fp16 converts
// ---------------------------------------------------------------------------
__global__ void conv_h(const float* __restrict__ in, __half* __restrict__ out, int n4)
{
    int i = blockIdx.x * blockDim.x + threadIdx.x;
    if (i >= n4) return;
    float4 v = ((const float4*)in)[i];
    ((__half2*)out)[2*i]   = __floats2half2_rn(v.x, v.y);
    ((__half2*)out)[2*i+1] = __floats2half2_rn(v.z, v.w);
}

__global__ void conv_w4(const float* __restrict__ a, const float* __restrict__ b,
                        const float* __restrict__ c, const float* __restrict__ d,
                        __half* __restrict__ out, int n4)
{
    int i = blockIdx.x * blockDim.x + threadIdx.x;
    if (i >= 4 * n4) return;
    int seg = i / n4;
    int j = i - seg * n4;
    const float* src = (seg == 0) ? a : (seg == 1) ? b : (seg == 2) ? c : d;
    float4 v = ((const float4*)src)[j];
    ((__half2*)out)[(size_t)seg * n4 * 2 + 2 * j]     = __floats2half2_rn(v.x, v.y);
    ((__half2*)out)[(size_t)seg * n4 * 2 + 2 * j + 1] = __floats2half2_rn(v.z, v.w);
}

// ---------------------------------------------------------------------------
// Pure-fp16 HMMA GEMM (unchanged from R7 except Q scale constant)
// ---------------------------------------------------------------------------
#define TILE_B   10240
#define STAGE_B  20480
#define GEMM_SMEM (3*STAGE_B)
#define NCHUNK   (D_/32)

template<int MODE>
__global__ __launch_bounds__(256)
void gemm_mma(const __half* __restrict__ X, const __half* __restrict__ W,
              const float* __restrict__ bias, float* __restrict__ outF,
              __half* __restrict__ oQ, __half* __restrict__ oK, __half* __restrict__ oV)
{
    extern __shared__ __align__(128) char smem[];
    const int tid  = threadIdx.x;
    const int lane = tid & 31;
    const int wid  = tid >> 5;
    const int m0 = blockIdx.y * 128;
    const int n0 = blockIdx.x * 128;
    const int wm = (wid & 1) * 64;
    const int wn = (wid >> 1) * 32;
    const uint32_t sb = smem_u32(smem);

    const uint32_t aOff = (uint32_t)((lane & 15) * 80 + (lane >> 4) * 16);
    const uint32_t bOff = (uint32_t)(((lane & 7) + (lane >> 4) * 8) * 80 + ((lane >> 3) & 1) * 16);

    float acc[4][4][4];
#pragma unroll
    for (int i = 0; i < 4; i++)
#pragma unroll
        for (int j = 0; j < 4; j++)
#pragma unroll
            for (int q = 0; q < 4; q++) acc[i][j][q] = 0.f;

    auto issue_stage = [&](int c) {
        const uint32_t stage = sb + (uint32_t)(c % 3) * STAGE_B;
        const int kt = c * 32;
#pragma unroll
        for (int i = 0; i < 4; i++) {
            const int idx = i * 256 + tid;
            const int tileI = idx >> 9;
            const int loc = idx & 511;
            const int row = loc >> 2;
            const int ch  = loc & 3;
            const __half* g = (tileI == 0) ? (X + (size_t)(m0 + row) * D_ + kt + ch * 8)
                                           : (W + (size_t)(n0 + row) * D_ + kt + ch * 8);
            cp_async16(stage + (uint32_t)(tileI * TILE_B + row * 80 + ch * 16), g);
        }
        CP_COMMIT();
    };

    issue_stage(0);
    issue_stage(1);

    for (int c = 0; c < NCHUNK; ++c) {
        CP_WAIT(1);
        __syncthreads();
        if (c + 2 < NCHUNK) issue_stage(c + 2);

        const uint32_t st = sb + (uint32_t)(c % 3) * STAGE_B;
        const uint32_t aT = st + (uint32_t)wm * 80 + aOff;
        const uint32_t bT = st + TILE_B + (uint32_t)wn * 80 + bOff;

#pragma unroll
        for (int ks = 0; ks < 2; ks++) {
            const uint32_t ka = (uint32_t)ks * 32;
            uint32_t ah[4][4], bh[2][4];
#pragma unroll
            for (int mt = 0; mt < 4; mt++) ldsm4(aT + (uint32_t)mt * (16 * 80) + ka, ah[mt]);
#pragma unroll
            for (int p = 0; p < 2; p++)    ldsm4(bT + (uint32_t)p * (16 * 80) + ka, bh[p]);
#pragma unroll
            for (int mt = 0; mt < 4; mt++)
#pragma unroll
                for (int nt = 0; nt < 4; nt++)
                    mma_f16(acc[mt][nt], ah[mt], &bh[nt >> 1][(nt & 1) * 2]);
        }
    }

    const int g = lane >> 2;
    const int t = lane & 3;
    if (MODE == 0) {
        const int proj = n0 >> 10;
        __half* dst = (proj == 0) ? oQ : (proj == 1) ? oK : oV;
        const float scl = (proj == 0) ? QSCL_ : 1.0f;
        const int cb = n0 & 1023;
#pragma unroll
        for (int mt = 0; mt < 4; mt++) {
            const int r0 = m0 + wm + mt * 16 + g;
            const int r1 = r0 + 8;
            const int b0i = r0 >> 11, s0 = r0 & 2047;
            const int b1i = r1 >> 11, s1 = r1 & 2047;
#pragma unroll
            for (int nt = 0; nt < 4; nt++) {
                const int cc = cb + wn + nt * 8 + t * 2;
                const int h = cc >> 6, d = cc & 63;
                __half2 v0 = __floats2half2_rn(acc[mt][nt][0] * scl, acc[mt][nt][1] * scl);
                __half2 v1 = __floats2half2_rn(acc[mt][nt][2] * scl, acc[mt][nt][3] * scl);
                *(__half2*)(dst + (((size_t)(b0i * H_ + h) * S_ + s0) * DH_ + d)) = v0;
                *(__half2*)(dst + (((size_t)(b1i * H_ + h) * S_ + s1) * DH_ + d)) = v1;
            }
        }
    } else {
#pragma unroll
        for (int mt = 0; mt < 4; mt++) {
            const int r0 = m0 + wm + mt * 16 + g;
            const int r1 = r0 + 8;
#pragma unroll
            for (int nt = 0; nt < 4; nt++) {
                const int col = n0 + wn + nt * 8 + t * 2;
                float2 bv = *(const float2*)(bias + col);
                float2 v0 = make_float2(acc[mt][nt][0] + bv.x, acc[mt][nt][1] + bv.y);
                float2 v1 = make_float2(acc[mt][nt][2] + bv.x, acc[mt][nt][3] + bv.y);
                *(float2*)(outF + (size_t)r0 * D_ + col) = v0;
                *(float2*)(outF + (size_t)r1 * D_ + col) = v1;
            }
        }
    }
}

// ---------------------------------------------------------------------------
// HMMA flash attention, m32 warp tiles (4 warps, 128 thr, 128 queries/CTA)
// 128-key stages, 2-stage cp.async pipeline, exp2 softmax.
// Each K/V fragment load feeds 2 m16 fragments -> halved smem traffic/FLOP.
// ---------------------------------------------------------------------------
#define KSTR      144
#define Q_BYTES   (128*KSTR)            // 18432
#define KV_HALF2  (128*KSTR)            // 18432 (128 K rows or 128 V rows)
#define KV_STAGE2 (2*KV_HALF2)          // 36864
#define ATTN_SMEM (Q_BYTES + 2*KV_STAGE2)  // 92160
#define NIT2      (S_/128)              // 16

__global__ __launch_bounds__(128)
void attn_mma(const __half* __restrict__ Q, const __half* __restrict__ K,
              const __half* __restrict__ V, __half* __restrict__ Ah)
{
    extern __shared__ __align__(128) char smem[];
    const uint32_t sb = smem_u32(smem);
    const int tid  = threadIdx.x;
    const int lane = tid & 31;
    const int wid  = tid >> 5;       // 0..3
    const int bh = blockIdx.y;
    const int q0 = blockIdx.x * 128;
    const __half* Qp = Q + (size_t)bh * S_ * DH_;
    const __half* Kp = K + (size_t)bh * S_ * DH_;
    const __half* Vp = V + (size_t)bh * S_ * DH_;

    const uint32_t bOff = (uint32_t)(((lane & 7) + (lane >> 4) * 8) * KSTR + ((lane >> 3) & 1) * 16);
    const uint32_t vOff = (uint32_t)((lane & 15) * KSTR + (lane >> 4) * 16);

    auto issue_kv = [&](int c) {
        const uint32_t st = sb + Q_BYTES + (uint32_t)(c & 1) * KV_STAGE2;
        const int kt = c * 128;
#pragma unroll
        for (int i = 0; i < 16; i++) {
            int idx = tid + i * 128;         // 0..2047
            int row = (idx >> 3) & 127;
            int ch  = idx & 7;
            const __half* src = (idx < 1024) ? (Kp + (size_t)(kt + row) * DH_ + ch * 8)
                                             : (Vp + (size_t)(kt + row) * DH_ + ch * 8);
            uint32_t dst = st + (uint32_t)((idx < 1024 ? 0 : KV_HALF2) + row * KSTR + ch * 16);
            cp_async16(dst, src);
        }
        CP_COMMIT();
    };

    // prologue: group0 = Q + KV0, group1 = KV1
    {
#pragma unroll
        for (int i = 0; i < 8; i++) {
            int idx = tid + i * 128;         // 0..1023
            int row = idx >> 3, ch = idx & 7;
            cp_async16(sb + (uint32_t)(row * KSTR + ch * 16),
                       Qp + (size_t)(q0 + row) * DH_ + ch * 8);
        }
        const uint32_t st = sb + Q_BYTES;
#pragma unroll
        for (int i = 0; i < 16; i++) {
            int idx = tid + i * 128;
            int row = (idx >> 3) & 127;
            int ch  = idx & 7;
            const __half* src = (idx < 1024) ? (Kp + (size_t)row * DH_ + ch * 8)
                                             : (Vp + (size_t)row * DH_ + ch * 8);
            uint32_t dst = st + (uint32_t)((idx < 1024 ? 0 : KV_HALF2) + row * KSTR + ch * 16);
            cp_async16(dst, src);
        }
        CP_COMMIT();
    }
    issue_kv(1);

    uint32_t qf[2][4][4];
    float of[2][8][4];
#pragma unroll
    for (int mf = 0; mf < 2; mf++)
#pragma unroll
        for (int t = 0; t < 8; t++)
#pragma unroll
            for (int q = 0; q < 4; q++) of[mf][t][q] = 0.f;
    float mS[2][2], lS[2][2];
#pragma unroll
    for (int mf = 0; mf < 2; mf++) { mS[mf][0] = mS[mf][1] = -1e30f; lS[mf][0] = lS[mf][1] = 0.f; }

    for (int c = 0; c < NIT2; ++c) {
        CP_WAIT(1);
        __syncthreads();
        if (c == 0) {
#pragma unroll
            for (int mf = 0; mf < 2; mf++) {
                const uint32_t qAddr = sb +
                    (uint32_t)((wid * 32 + mf * 16 + (lane & 15)) * KSTR + (lane >> 4) * 16);
#pragma unroll
                for (int kf = 0; kf < 4; kf++) ldsm4(qAddr + (uint32_t)kf * 32, qf[mf][kf]);
            }
        }
        const uint32_t stg = sb + Q_BYTES + (uint32_t)(c & 1) * KV_STAGE2;

#pragma unroll
        for (int sub = 0; sub < 2; sub++) {
            const uint32_t Kst = stg + (uint32_t)sub * (64 * KSTR);
            const uint32_t Vst = stg + KV_HALF2 + (uint32_t)sub * (64 * KSTR);

            // ---- S = Q K^T (64 keys, both m16 frags share kb) ----
            float sf[2][8][4];
#pragma unroll
            for (int mf = 0; mf < 2; mf++)
#pragma unroll
                for (int t = 0; t < 8; t++)
#pragma unroll
                    for (int q = 0; q < 4; q++) sf[mf][t][q] = 0.f;
#pragma unroll
            for (int kf = 0; kf < 4; kf++) {
                uint32_t kb[4][4];
#pragma unroll
                for (int kg = 0; kg < 4; kg++)
                    ldsm4(Kst + (uint32_t)(kg * 16 * KSTR) + (uint32_t)kf * 32 + bOff, kb[kg]);
#pragma unroll
                for (int mf = 0; mf < 2; mf++)
#pragma unroll
                    for (int kg = 0; kg < 4; kg++) {
                        mma_f16(sf[mf][2 * kg],     qf[mf][kf], &kb[kg][0]);
                        mma_f16(sf[mf][2 * kg + 1], qf[mf][kf], &kb[kg][2]);
                    }
            }

            // ---- online softmax (base-2) + pack P ----
            uint32_t pa[2][4][4];
#pragma unroll
            for (int mf = 0; mf < 2; mf++) {
                float mt_lo = -1e30f, mt_hi = -1e30f;
#pragma unroll
                for (int t = 0; t < 8; t++) {
                    mt_lo = fmaxf(mt_lo, fmaxf(sf[mf][t][0], sf[mf][t][1]));
                    mt_hi = fmaxf(mt_hi, fmaxf(sf[mf][t][2], sf[mf][t][3]));
                }
                mt_lo = fmaxf(mt_lo, __shfl_xor_sync(0xffffffffu, mt_lo, 1));
                mt_lo = fmaxf(mt_lo, __shfl_xor_sync(0xffffffffu, mt_lo, 2));
                mt_hi = fmaxf(mt_hi, __shfl_xor_sync(0xffffffffu, mt_hi, 1));
                mt_hi = fmaxf(mt_hi, __shfl_xor_sync(0xffffffffu, mt_hi, 2));
                const float mn_lo = fmaxf(mS[mf][0], mt_lo);
                const float mn_hi = fmaxf(mS[mf][1], mt_hi);
                const float corr_lo = ex2f(mS[mf][0] - mn_lo);
                const float corr_hi = ex2f(mS[mf][1] - mn_hi);
                mS[mf][0] = mn_lo; mS[mf][1] = mn_hi;

                float ls_lo = 0.f, ls_hi = 0.f;
#pragma unroll
                for (int t = 0; t < 8; t++) {
                    sf[mf][t][0] = ex2f(sf[mf][t][0] - mn_lo);
                    sf[mf][t][1] = ex2f(sf[mf][t][1] - mn_lo);
                    sf[mf][t][2] = ex2f(sf[mf][t][2] - mn_hi);
                    sf[mf][t][3] = ex2f(sf[mf][t][3] - mn_hi);
                    ls_lo += sf[mf][t][0] + sf[mf][t][1];
                    ls_hi += sf[mf][t][2] + sf[mf][t][3];
                }
                lS[mf][0] = lS[mf][0] * corr_lo + ls_lo;
                lS[mf][1] = lS[mf][1] * corr_hi + ls_hi;
#pragma unroll
                for (int t = 0; t < 8; t++) {
                    of[mf][t][0] *= corr_lo; of[mf][t][1] *= corr_lo;
                    of[mf][t][2] *= corr_hi; of[mf][t][3] *= corr_hi;
                }
#pragma unroll
                for (int kf = 0; kf < 4; kf++) {
                    pa[mf][kf][0] = h2_u32(__floats2half2_rn(sf[mf][2 * kf][0],     sf[mf][2 * kf][1]));
                    pa[mf][kf][1] = h2_u32(__floats2half2_rn(sf[mf][2 * kf][2],     sf[mf][2 * kf][3]));
                    pa[mf][kf][2] = h2_u32(__floats2half2_rn(sf[mf][2 * kf + 1][0], sf[mf][2 * kf + 1][1]));
                    pa[mf][kf][3] = h2_u32(__floats2half2_rn(sf[mf][2 * kf + 1][2], sf[mf][2 * kf + 1][3]));
                }
            }

            // ---- O += P V (both m16 frags share vb) ----
#pragma unroll
            for (int kf = 0; kf < 4; kf++) {
                uint32_t vb[4][4];
#pragma unroll
                for (int ng = 0; ng < 4; ng++)
                    ldsm4t(Vst + (uint32_t)(kf * 16 * KSTR) + (uint32_t)(ng * 32) + vOff, vb[ng]);
#pragma unroll
                for (int mf = 0; mf < 2; mf++)
#pragma unroll
                    for (int ng = 0; ng < 4; ng++) {
                        mma_f16(of[mf][2 * ng],     pa[mf][kf], &vb[ng][0]);
                        mma_f16(of[mf][2 * ng + 1], pa[mf][kf], &vb[ng][2]);
                    }
            }
        }
        __syncthreads();
        if (c + 2 < NIT2) issue_kv(c + 2);
    }

    // ---- epilogue ----
    const int b = bh >> 4;
    const int h = bh & 15;
#pragma unroll
    for (int mf = 0; mf < 2; mf++) {
        float l_lo = lS[mf][0], l_hi = lS[mf][1];
        l_lo += __shfl_xor_sync(0xffffffffu, l_lo, 1);
        l_lo += __shfl_xor_sync(0xffffffffu, l_lo, 2);
        l_hi += __shfl_xor_sync(0xffffffffu, l_hi, 1);
        l_hi += __shfl_xor_sync(0xffffffffu, l_hi, 2);
        const float inv_lo = 1.f / l_lo;
        const float inv_hi = 1.f / l_hi;
        const int row0 = q0 + wid * 32 + mf * 16 + (lane >> 2);
        const int row1 = row0 + 8;
#pragma unroll
        for (int t = 0; t < 8; t++) {
            const int colG = h * DH_ + t * 8 + (lane & 3) * 2;
            size_t a0 = (size_t)(b * S_ + row0) * D_ + colG;
            size_t a1 = (size_t)(b * S_ + row1) * D_ + colG;
            *(__half2*)(Ah + a0) = __floats2half2_rn(of[mf][t][0] * inv_lo, of[mf][t][1] * inv_lo);
            *(__half2*)(Ah + a1) = __floats2half2_rn(of[mf][t][2] * inv_hi, of[mf][t][3] * inv_hi);
        }
    }
}

// ---------------------------------------------------------------------------
extern "C" void kernel_launch(void* const* d_in, const int* in_sizes, int n_in,
                              void* d_out, int out_size)
{
    const float* x  = (const float*)d_in[0];
    const float* Wq = (const float*)d_in[1];
    const float* Wk = (const float*)d_in[2];
    const float* Wv = (const float*)d_in[3];
    const float* Wo = (const float*)d_in[4];
    const float* bo = (const float*)d_in[5];
    float* out = (float*)d_out;

    __half *Qh, *Kh, *Vh, *Xh, *Wf, *Ah;
    cudaGetSymbolAddress((void**)&Qh, g_Qh);
    cudaGetSymbolAddress((void**)&Kh, g_Kh);
    cudaGetSymbolAddress((void**)&Vh, g_Vh);
    cudaGetSymbolAddress((void**)&Xh, g_Xh);
    cudaGetSymbolAddress((void**)&Wf, g_Wf);
    cudaGetSymbolAddress((void**)&Ah, g_Ah);

    static bool attr_set = false;
    if (!attr_set) {
        cudaFuncSetAttribute(gemm_mma<0>, cudaFuncAttributeMaxDynamicSharedMemorySize, GEMM_SMEM);
        cudaFuncSetAttribute(gemm_mma<1>, cudaFuncAttributeMaxDynamicSharedMemorySize, GEMM_SMEM);
        cudaFuncSetAttribute(attn_mma,    cudaFuncAttributeMaxDynamicSharedMemorySize, ATTN_SMEM);
        attr_set = true;
    }

    const int nX4 = M_ * D_ / 4;
    const int nW4 = D_ * D_ / 4;
    conv_h<<<(nX4 + 255) / 256, 256>>>(x, Xh, nX4);
    conv_w4<<<(4 * nW4 + 255) / 256, 256>>>(Wq, Wk, Wv, Wo, Wf, nW4);

    gemm_mma<0><<<dim3(3 * D_ / 128, M_ / 128), 256, GEMM_SMEM>>>(
        Xh, Wf, nullptr, nullptr, Qh, Kh, Vh);

    attn_mma<<<dim3(S_ / 128, B_ * H_), 128, ATTN_SMEM>>>(Qh, Kh, Vh, Ah);

    gemm_mma<1><<<dim3(D_ / 128, M_ / 128), 256, GEMM_SMEM>>>(
        Ah, Wf + 3 * (size_t)D_ * D_, bo, out, nullptr, nullptr, nullptr);
}

// round 10
// speedup vs baseline: 8.2921x; 1.0195x over previous
#include <cuda_runtime.h>
#include <cuda_fp16.h>
#include <stdint.h>
#include <math.h>

// Problem constants
#define B_  2
#define S_  2048
#define D_  1024
#define H_  16
#define DH_ 64
#define M_  (B_*S_)          // 4096
#define QSCL_ 0.18033688f    // 0.125 * log2(e)

// ---------------------------------------------------------------------------
// Scratch (__device__ globals; allocation-free rule)
// ---------------------------------------------------------------------------
static __device__ __half g_Qh[B_*H_*S_*DH_];   // [b][h][s][dh] fp16, scaled by QSCL_
static __device__ __half g_Kh[B_*H_*S_*DH_];
static __device__ __half g_Vh[B_*H_*S_*DH_];
static __device__ __half g_Xh[M_*D_];
static __device__ __half g_Wf[4*D_*D_];
static __device__ __half g_Ah[M_*D_];

// ---------------------------------------------------------------------------
// Helpers
// ---------------------------------------------------------------------------
__device__ __forceinline__ uint32_t smem_u32(const void* p) {
    uint32_t a;
    asm("{ .reg .u64 t; cvta.to.shared.u64 t, %1; cvt.u32.u64 %0, t; }" : "=r"(a) : "l"(p));
    return a;
}
__device__ __forceinline__ uint32_t h2_u32(__half2 h) {
    union { __half2 h; uint32_t u; } cvt;
    cvt.h = h;
    return cvt.u;
}
__device__ __forceinline__ float ex2f(float x) {
    float y;
    asm("ex2.approx.ftz.f32 %0, %1;" : "=f"(y) : "f"(x));
    return y;
}
__device__ __forceinline__ void ldsm4(uint32_t addr, uint32_t* r) {
    asm volatile("ldmatrix.sync.aligned.m8n8.x4.shared.b16 {%0,%1,%2,%3}, [%4];"
                 : "=r"(r[0]), "=r"(r[1]), "=r"(r[2]), "=r"(r[3]) : "r"(addr));
}
__device__ __forceinline__ void ldsm4t(uint32_t addr, uint32_t* r) {
    asm volatile("ldmatrix.sync.aligned.m8n8.x4.trans.shared.b16 {%0,%1,%2,%3}, [%4];"
                 : "=r"(r[0]), "=r"(r[1]), "=r"(r[2]), "=r"(r[3]) : "r"(addr));
}
__device__ __forceinline__ void mma_f16(float* d, const uint32_t* a, const uint32_t* b) {
    asm volatile("mma.sync.aligned.m16n8k16.row.col.f32.f16.f16.f32 "
                 "{%0,%1,%2,%3},{%4,%5,%6,%7},{%8,%9},{%0,%1,%2,%3};"
                 : "+f"(d[0]), "+f"(d[1]), "+f"(d[2]), "+f"(d[3])
                 : "r"(a[0]), "r"(a[1]), "r"(a[2]), "r"(a[3]), "r"(b[0]), "r"(b[1]));
}
__device__ __forceinline__ void cp_async16(uint32_t dst, const void* src) {
    asm volatile("cp.async.cg.shared.global [%0], [%1], 16;" :: "r"(dst), "l"(src));
}
#define CP_COMMIT() asm volatile("cp.async.commit_group;" ::: "memory")
#define CP_WAIT(n)  asm volatile("cp.async.wait_group %0;" :: "n"(n) : "memory")

// ---------------------------------------------------------------------------
// Merged fp32 -> fp16 convert: hidden_states + 4 weight matrices
// ---------------------------------------------------------------------------
__global__ void conv_all(const float* __restrict__ x,
                         const float* __restrict__ wq, const float* __restrict__ wk,
                         const float* __restrict__ wv, const float* __restrict__ wo,
                         __half* __restrict__ xo, __half* __restrict__ wf,
                         int nX4, int nW4)
{
    int i = blockIdx.x * blockDim.x + threadIdx.x;
    if (i < nX4) {
        float4 v = ((const float4*)x)[i];
        ((__half2*)xo)[2*i]   = __floats2half2_rn(v.x, v.y);
        ((__half2*)xo)[2*i+1] = __floats2half2_rn(v.z, v.w);
    } else {
        int j = i - nX4;
        if (j >= 4 * nW4) return;
        int seg = j / nW4;
        int k = j - seg * nW4;
        const float* src = (seg == 0) ? wq : (seg == 1) ? wk : (seg == 2) ? wv : wo;
        float4 v = ((const float4*)src)[k];
        ((__half2*)wf)[(size_t)seg * nW4 * 2 + 2 * k]     = __floats2half2_rn(v.x, v.y);
        ((__half2*)wf)[(size_t)seg * nW4 * 2 + 2 * k + 1] = __floats2half2_rn(v.z, v.w);
    }
}

// ---------------------------------------------------------------------------
// Pure-fp16 HMMA GEMM (unchanged)
// ---------------------------------------------------------------------------
#define TILE_B   10240
#define STAGE_B  20480
#define GEMM_SMEM (3*STAGE_B)
#define NCHUNK   (D_/32)

template<int MODE>
__global__ __launch_bounds__(256)
void gemm_mma(const __half* __restrict__ X, const __half* __restrict__ W,
              const float* __restrict__ bias, float* __restrict__ outF,
              __half* __restrict__ oQ, __half* __restrict__ oK, __half* __restrict__ oV)
{
    extern __shared__ __align__(128) char smem[];
    const int tid  = threadIdx.x;
    const int lane = tid & 31;
    const int wid  = tid >> 5;
    const int m0 = blockIdx.y * 128;
    const int n0 = blockIdx.x * 128;
    const int wm = (wid & 1) * 64;
    const int wn = (wid >> 1) * 32;
    const uint32_t sb = smem_u32(smem);

    const uint32_t aOff = (uint32_t)((lane & 15) * 80 + (lane >> 4) * 16);
    const uint32_t bOff = (uint32_t)(((lane & 7) + (lane >> 4) * 8) * 80 + ((lane >> 3) & 1) * 16);

    float acc[4][4][4];
#pragma unroll
    for (int i = 0; i < 4; i++)
#pragma unroll
        for (int j = 0; j < 4; j++)
#pragma unroll
            for (int q = 0; q < 4; q++) acc[i][j][q] = 0.f;

    auto issue_stage = [&](int c) {
        const uint32_t stage = sb + (uint32_t)(c % 3) * STAGE_B;
        const int kt = c * 32;
#pragma unroll
        for (int i = 0; i < 4; i++) {
            const int idx = i * 256 + tid;
            const int tileI = idx >> 9;
            const int loc = idx & 511;
            const int row = loc >> 2;
            const int ch  = loc & 3;
            const __half* g = (tileI == 0) ? (X + (size_t)(m0 + row) * D_ + kt + ch * 8)
                                           : (W + (size_t)(n0 + row) * D_ + kt + ch * 8);
            cp_async16(stage + (uint32_t)(tileI * TILE_B + row * 80 + ch * 16), g);
        }
        CP_COMMIT();
    };

    issue_stage(0);
    issue_stage(1);

    for (int c = 0; c < NCHUNK; ++c) {
        CP_WAIT(1);
        __syncthreads();
        if (c + 2 < NCHUNK) issue_stage(c + 2);

        const uint32_t st = sb + (uint32_t)(c % 3) * STAGE_B;
        const uint32_t aT = st + (uint32_t)wm * 80 + aOff;
        const uint32_t bT = st + TILE_B + (uint32_t)wn * 80 + bOff;

#pragma unroll
        for (int ks = 0; ks < 2; ks++) {
            const uint32_t ka = (uint32_t)ks * 32;
            uint32_t ah[4][4], bh[2][4];
#pragma unroll
            for (int mt = 0; mt < 4; mt++) ldsm4(aT + (uint32_t)mt * (16 * 80) + ka, ah[mt]);
#pragma unroll
            for (int p = 0; p < 2; p++)    ldsm4(bT + (uint32_t)p * (16 * 80) + ka, bh[p]);
#pragma unroll
            for (int mt = 0; mt < 4; mt++)
#pragma unroll
                for (int nt = 0; nt < 4; nt++)
                    mma_f16(acc[mt][nt], ah[mt], &bh[nt >> 1][(nt & 1) * 2]);
        }
    }

    const int g = lane >> 2;
    const int t = lane & 3;
    if (MODE == 0) {
        const int proj = n0 >> 10;
        __half* dst = (proj == 0) ? oQ : (proj == 1) ? oK : oV;
        const float scl = (proj == 0) ? QSCL_ : 1.0f;
        const int cb = n0 & 1023;
#pragma unroll
        for (int mt = 0; mt < 4; mt++) {
            const int r0 = m0 + wm + mt * 16 + g;
            const int r1 = r0 + 8;
            const int b0i = r0 >> 11, s0 = r0 & 2047;
            const int b1i = r1 >> 11, s1 = r1 & 2047;
#pragma unroll
            for (int nt = 0; nt < 4; nt++) {
                const int cc = cb + wn + nt * 8 + t * 2;
                const int h = cc >> 6, d = cc & 63;
                __half2 v0 = __floats2half2_rn(acc[mt][nt][0] * scl, acc[mt][nt][1] * scl);
                __half2 v1 = __floats2half2_rn(acc[mt][nt][2] * scl, acc[mt][nt][3] * scl);
                *(__half2*)(dst + (((size_t)(b0i * H_ + h) * S_ + s0) * DH_ + d)) = v0;
                *(__half2*)(dst + (((size_t)(b1i * H_ + h) * S_ + s1) * DH_ + d)) = v1;
            }
        }
    } else {
#pragma unroll
        for (int mt = 0; mt < 4; mt++) {
            const int r0 = m0 + wm + mt * 16 + g;
            const int r1 = r0 + 8;
#pragma unroll
            for (int nt = 0; nt < 4; nt++) {
                const int col = n0 + wn + nt * 8 + t * 2;
                float2 bv = *(const float2*)(bias + col);
                float2 v0 = make_float2(acc[mt][nt][0] + bv.x, acc[mt][nt][1] + bv.y);
                float2 v1 = make_float2(acc[mt][nt][2] + bv.x, acc[mt][nt][3] + bv.y);
                *(float2*)(outF + (size_t)r0 * D_ + col) = v0;
                *(float2*)(outF + (size_t)r1 * D_ + col) = v1;
            }
        }
    }
}

// ---------------------------------------------------------------------------
// HMMA flash attention: 8 warps x m32 = 256 queries/CTA, 256 threads.
// 128-key stages, 2-stage cp.async pipeline, exp2 softmax.
// 2 warps/SMSP restores softmax<->MMA overlap; K/V frags still shared by 2 m16.
// ---------------------------------------------------------------------------
#define KSTR      144
#define Q_BYTES   (256*KSTR)            // 36864
#define KV_HALF2  (128*KSTR)            // 18432
#define KV_STAGE2 (2*KV_HALF2)          // 36864
#define ATTN_SMEM (Q_BYTES + 2*KV_STAGE2)  // 110592
#define NIT2      (S_/128)              // 16

__global__ __launch_bounds__(256)
void attn_mma(const __half* __restrict__ Q, const __half* __restrict__ K,
              const __half* __restrict__ V, __half* __restrict__ Ah)
{
    extern __shared__ __align__(128) char smem[];
    const uint32_t sb = smem_u32(smem);
    const int tid  = threadIdx.x;
    const int lane = tid & 31;
    const int wid  = tid >> 5;       // 0..7
    const int bh = blockIdx.y;
    const int q0 = blockIdx.x * 256;
    const __half* Qp = Q + (size_t)bh * S_ * DH_;
    const __half* Kp = K + (size_t)bh * S_ * DH_;
    const __half* Vp = V + (size_t)bh * S_ * DH_;

    const uint32_t bOff = (uint32_t)(((lane & 7) + (lane >> 4) * 8) * KSTR + ((lane >> 3) & 1) * 16);
    const uint32_t vOff = (uint32_t)((lane & 15) * KSTR + (lane >> 4) * 16);

    auto issue_kv = [&](int c) {
        const uint32_t st = sb + Q_BYTES + (uint32_t)(c & 1) * KV_STAGE2;
        const int kt = c * 128;
#pragma unroll
        for (int i = 0; i < 8; i++) {
            int idx = tid + i * 256;         // 0..2047
            int row = (idx >> 3) & 127;
            int ch  = idx & 7;
            const __half* src = (idx < 1024) ? (Kp + (size_t)(kt + row) * DH_ + ch * 8)
                                             : (Vp + (size_t)(kt + row) * DH_ + ch * 8);
            uint32_t dst = st + (uint32_t)((idx < 1024 ? 0 : KV_HALF2) + row * KSTR + ch * 16);
            cp_async16(dst, src);
        }
        CP_COMMIT();
    };

    // prologue: group0 = Q + KV0, group1 = KV1
    {
#pragma unroll
        for (int i = 0; i < 8; i++) {
            int idx = tid + i * 256;         // 0..2047 (256 rows x 8 chunks)
            int row = idx >> 3, ch = idx & 7;
            cp_async16(sb + (uint32_t)(row * KSTR + ch * 16),
                       Qp + (size_t)(q0 + row) * DH_ + ch * 8);
        }
        const uint32_t st = sb + Q_BYTES;
#pragma unroll
        for (int i = 0; i < 8; i++) {
            int idx = tid + i * 256;
            int row = (idx >> 3) & 127;
            int ch  = idx & 7;
            const __half* src = (idx < 1024) ? (Kp + (size_t)row * DH_ + ch * 8)
                                             : (Vp + (size_t)row * DH_ + ch * 8);
            uint32_t dst = st + (uint32_t)((idx < 1024 ? 0 : KV_HALF2) + row * KSTR + ch * 16);
            cp_async16(dst, src);
        }
        CP_COMMIT();
    }
    issue_kv(1);

    uint32_t qf[2][4][4];
    float of[2][8][4];
#pragma unroll
    for (int mf = 0; mf < 2; mf++)
#pragma unroll
        for (int t = 0; t < 8; t++)
#pragma unroll
            for (int q = 0; q < 4; q++) of[mf][t][q] = 0.f;
    float mS[2][2], lS[2][2];
#pragma unroll
    for (int mf = 0; mf < 2; mf++) { mS[mf][0] = mS[mf][1] = -1e30f; lS[mf][0] = lS[mf][1] = 0.f; }

    for (int c = 0; c < NIT2; ++c) {
        CP_WAIT(1);
        __syncthreads();
        if (c == 0) {
#pragma unroll
            for (int mf = 0; mf < 2; mf++) {
                const uint32_t qAddr = sb +
                    (uint32_t)((wid * 32 + mf * 16 + (lane & 15)) * KSTR + (lane >> 4) * 16);
#pragma unroll
                for (int kf = 0; kf < 4; kf++) ldsm4(qAddr + (uint32_t)kf * 32, qf[mf][kf]);
            }
        }
        const uint32_t stg = sb + Q_BYTES + (uint32_t)(c & 1) * KV_STAGE2;

#pragma unroll
        for (int sub = 0; sub < 2; sub++) {
            const uint32_t Kst = stg + (uint32_t)sub * (64 * KSTR);
            const uint32_t Vst = stg + KV_HALF2 + (uint32_t)sub * (64 * KSTR);

            float sf[2][8][4];
#pragma unroll
            for (int mf = 0; mf < 2; mf++)
#pragma unroll
                for (int t = 0; t < 8; t++)
#pragma unroll
                    for (int q = 0; q < 4; q++) sf[mf][t][q] = 0.f;
#pragma unroll
            for (int kf = 0; kf < 4; kf++) {
                uint32_t kb[4][4];
#pragma unroll
                for (int kg = 0; kg < 4; kg++)
                    ldsm4(Kst + (uint32_t)(kg * 16 * KSTR) + (uint32_t)kf * 32 + bOff, kb[kg]);
#pragma unroll
                for (int mf = 0; mf < 2; mf++)
#pragma unroll
                    for (int kg = 0; kg < 4; kg++) {
                        mma_f16(sf[mf][2 * kg],     qf[mf][kf], &kb[kg][0]);
                        mma_f16(sf[mf][2 * kg + 1], qf[mf][kf], &kb[kg][2]);
                    }
            }

            uint32_t pa[2][4][4];
#pragma unroll
            for (int mf = 0; mf < 2; mf++) {
                float mt_lo = -1e30f, mt_hi = -1e30f;
#pragma unroll
                for (int t = 0; t < 8; t++) {
                    mt_lo = fmaxf(mt_lo, fmaxf(sf[mf][t][0], sf[mf][t][1]));
                    mt_hi = fmaxf(mt_hi, fmaxf(sf[mf][t][2], sf[mf][t][3]));
                }
                mt_lo = fmaxf(mt_lo, __shfl_xor_sync(0xffffffffu, mt_lo, 1));
                mt_lo = fmaxf(mt_lo, __shfl_xor_sync(0xffffffffu, mt_lo, 2));
                mt_hi = fmaxf(mt_hi, __shfl_xor_sync(0xffffffffu, mt_hi, 1));
                mt_hi = fmaxf(mt_hi, __shfl_xor_sync(0xffffffffu, mt_hi, 2));
                const float mn_lo = fmaxf(mS[mf][0], mt_lo);
                const float mn_hi = fmaxf(mS[mf][1], mt_hi);
                const float corr_lo = ex2f(mS[mf][0] - mn_lo);
                const float corr_hi = ex2f(mS[mf][1] - mn_hi);
                mS[mf][0] = mn_lo; mS[mf][1] = mn_hi;

                float ls_lo = 0.f, ls_hi = 0.f;
#pragma unroll
                for (int t = 0; t < 8; t++) {
                    sf[mf][t][0] = ex2f(sf[mf][t][0] - mn_lo);
                    sf[mf][t][1] = ex2f(sf[mf][t][1] - mn_lo);
                    sf[mf][t][2] = ex2f(sf[mf][t][2] - mn_hi);
                    sf[mf][t][3] = ex2f(sf[mf][t][3] - mn_hi);
                    ls_lo += sf[mf][t][0] + sf[mf][t][1];
                    ls_hi += sf[mf][t][2] + sf[mf][t][3];
                }
                lS[mf][0] = lS[mf][0] * corr_lo + ls_lo;
                lS[mf][1] = lS[mf][1] * corr_hi + ls_hi;
#pragma unroll
                for (int t = 0; t < 8; t++) {
                    of[mf][t][0] *= corr_lo; of[mf][t][1] *= corr_lo;
                    of[mf][t][2] *= corr_hi; of[mf][t][3] *= corr_hi;
                }
#pragma unroll
                for (int kf = 0; kf < 4; kf++) {
                    pa[mf][kf][0] = h2_u32(__floats2half2_rn(sf[mf][2 * kf][0],     sf[mf][2 * kf][1]));
                    pa[mf][kf][1] = h2_u32(__floats2half2_rn(sf[mf][2 * kf][2],     sf[mf][2 * kf][3]));
                    pa[mf][kf][2] = h2_u32(__floats2half2_rn(sf[mf][2 * kf + 1][0], sf[mf][2 * kf + 1][1]));
                    pa[mf][kf][3] = h2_u32(__floats2half2_rn(sf[mf][2 * kf + 1][2], sf[mf][2 * kf + 1][3]));
                }
            }

#pragma unroll
            for (int kf = 0; kf < 4; kf++) {
                uint32_t vb[4][4];
#pragma unroll
                for (int ng = 0; ng < 4; ng++)
                    ldsm4t(Vst + (uint32_t)(kf * 16 * KSTR) + (uint32_t)(ng * 32) + vOff, vb[ng]);
#pragma unroll
                for (int mf = 0; mf < 2; mf++)
#pragma unroll
                    for (int ng = 0; ng < 4; ng++) {
                        mma_f16(of[mf][2 * ng],     pa[mf][kf], &vb[ng][0]);
                        mma_f16(of[mf][2 * ng + 1], pa[mf][kf], &vb[ng][2]);
                    }
            }
        }
        __syncthreads();
        if (c + 2 < NIT2) issue_kv(c + 2);
    }

    // ---- epilogue ----
    const int b = bh >> 4;
    const int h = bh & 15;
#pragma unroll
    for (int mf = 0; mf < 2; mf++) {
        float l_lo = lS[mf][0], l_hi = lS[mf][1];
        l_lo += __shfl_xor_sync(0xffffffffu, l_lo, 1);
        l_lo += __shfl_xor_sync(0xffffffffu, l_lo, 2);
        l_hi += __shfl_xor_sync(0xffffffffu, l_hi, 1);
        l_hi += __shfl_xor_sync(0xffffffffu, l_hi, 2);
        const float inv_lo = 1.f / l_lo;
        const float inv_hi = 1.f / l_hi;
        const int row0 = q0 + wid * 32 + mf * 16 + (lane >> 2);
        const int row1 = row0 + 8;
#pragma unroll
        for (int t = 0; t < 8; t++) {
            const int colG = h * DH_ + t * 8 + (lane & 3) * 2;
            size_t a0 = (size_t)(b * S_ + row0) * D_ + colG;
            size_t a1 = (size_t)(b * S_ + row1) * D_ + colG;
            *(__half2*)(Ah + a0) = __floats2half2_rn(of[mf][t][0] * inv_lo, of[mf][t][1] * inv_lo);
            *(__half2*)(Ah + a1) = __floats2half2_rn(of[mf][t][2] * inv_hi, of[mf][t][3] * inv_hi);
        }
    }
}

// ---------------------------------------------------------------------------
extern "C" void kernel_launch(void* const* d_in, const int* in_sizes, int n_in,
                              void* d_out, int out_size)
{
    const float* x  = (const float*)d_in[0];
    const float* Wq = (const float*)d_in[1];
    const float* Wk = (const float*)d_in[2];
    const float* Wv = (const float*)d_in[3];
    const float* Wo = (const float*)d_in[4];
    const float* bo = (const float*)d_in[5];
    float* out = (float*)d_out;

    __half *Qh, *Kh, *Vh, *Xh, *Wf, *Ah;
    cudaGetSymbolAddress((void**)&Qh, g_Qh);
    cudaGetSymbolAddress((void**)&Kh, g_Kh);
    cudaGetSymbolAddress((void**)&Vh, g_Vh);
    cudaGetSymbolAddress((void**)&Xh, g_Xh);
    cudaGetSymbolAddress((void**)&Wf, g_Wf);
    cudaGetSymbolAddress((void**)&Ah, g_Ah);

    static bool attr_set = false;
    if (!attr_set) {
        cudaFuncSetAttribute(gemm_mma<0>, cudaFuncAttributeMaxDynamicSharedMemorySize, GEMM_SMEM);
        cudaFuncSetAttribute(gemm_mma<1>, cudaFuncAttributeMaxDynamicSharedMemorySize, GEMM_SMEM);
        cudaFuncSetAttribute(attn_mma,    cudaFuncAttributeMaxDynamicSharedMemorySize, ATTN_SMEM);
        attr_set = true;
    }

    const int nX4 = M_ * D_ / 4;       // 1048576
    const int nW4 = D_ * D_ / 4;       // 262144
    conv_all<<<(nX4 + 4 * nW4 + 255) / 256, 256>>>(x, Wq, Wk, Wv, Wo, Xh, Wf, nX4, nW4);

    gemm_mma<0><<<dim3(3 * D_ / 128, M_ / 128), 256, GEMM_SMEM>>>(
        Xh, Wf, nullptr, nullptr, Qh, Kh, Vh);

    attn_mma<<<dim3(S_ / 256, B_ * H_), 256, ATTN_SMEM>>>(Qh, Kh, Vh, Ah);

    gemm_mma<1><<<dim3(D_ / 128, M_ / 128), 256, GEMM_SMEM>>>(
        Ah, Wf + 3 * (size_t)D_ * D_, bo, out, nullptr, nullptr, nullptr);
}